// round 10
// baseline (speedup 1.0000x reference)
#include <cuda_runtime.h>
#include <cuda_bf16.h>
#include <math.h>
#include <stdint.h>

#define NINT 37449
#define NVOC 32000

// ---------------- device scratch (no allocs allowed) ----------------
static __device__ float g_Pb[(size_t)NVOC * 128]; // emb@W_in + b_in
static __device__ float g_T [(size_t)NVOC * 128]; // tanh(Pb)
static __device__ float g_Q [(size_t)NVOC * 128]; // T@W_out
static __device__ float g_h [(size_t)NINT * 128]; // hidden, internal nodes
static __device__ uint4 g_Bfrag[3][4096];         // {Win,U,Wout}: {bh0,bh1,bl0,bl1} packed bf16x2

// smem: AsH[64][68] + AsL[64][68] packed bf16x2 (hi/lo split of A)
#define KP 68
#define SMEM_BYTES (64 * KP * 4 * 2)   // 34816

__device__ __forceinline__ uint32_t pack_bf(float v0, float v1) {
    uint32_t r;
    asm("cvt.rn.bf16x2.f32 %0, %1, %2;" : "=r"(r) : "f"(v1), "f"(v0));
    return r;
}
__device__ __forceinline__ float bfv(float v) {
    return __bfloat162float(__float2bfloat16(v));
}

__device__ __forceinline__ void store_k4(uint32_t* AsH, uint32_t* AsL,
                                         int row, int f4, float4 v) {
    float h0 = bfv(v.x), h1 = bfv(v.y), h2 = bfv(v.z), h3 = bfv(v.w);
    const int o = row * KP + f4 * 2;
    AsH[o]     = pack_bf(h0, h1);
    AsH[o + 1] = pack_bf(h2, h3);
    AsL[o]     = pack_bf(v.x - h0, v.y - h1);
    AsL[o + 1] = pack_bf(v.z - h2, v.w - h3);
}

__device__ __forceinline__ void mma16(float d[4], const uint32_t a[4],
                                      uint32_t b0, uint32_t b1) {
    asm volatile(
        "mma.sync.aligned.m16n8k16.row.col.f32.bf16.bf16.f32 "
        "{%0,%1,%2,%3}, {%4,%5,%6,%7}, {%8,%9}, {%0,%1,%2,%3};"
        : "+f"(d[0]), "+f"(d[1]), "+f"(d[2]), "+f"(d[3])
        : "r"(a[0]), "r"(a[1]), "r"(a[2]), "r"(a[3]), "r"(b0), "r"(b1));
}

// 64x128x128 tile GEMM, bf16 x3 (AhBh + AhBl + AlBh), A pre-split in smem.
// Warp (wr,wc): rows wr*16..+16, cols wc*64..+64.
// MMA ordering: 4-nt groups, dependency distance 4 (pipelined accumulators).
__device__ __forceinline__ void gemm64(const uint32_t* __restrict__ AsH,
                                       const uint32_t* __restrict__ AsL,
                                       const uint4* __restrict__ Bf,
                                       int wr, int wc, int lane,
                                       float acc[8][4])
{
    const int rA = wr * 16 + (lane >> 2);
    const int cA = lane & 3;
    const uint4* bp = Bf + (wc * 8) * 32 + lane;
#pragma unroll
    for (int ks = 0; ks < 8; ks++) {
        uint32_t ah[4], al[4];
        const int kpb = ks * 8 + cA;
        ah[0] = AsH[rA * KP + kpb];
        ah[1] = AsH[(rA + 8) * KP + kpb];
        ah[2] = AsH[rA * KP + kpb + 4];
        ah[3] = AsH[(rA + 8) * KP + kpb + 4];
        al[0] = AsL[rA * KP + kpb];
        al[1] = AsL[(rA + 8) * KP + kpb];
        al[2] = AsL[rA * KP + kpb + 4];
        al[3] = AsL[(rA + 8) * KP + kpb + 4];
#pragma unroll
        for (int g = 0; g < 2; g++) {
            const int nb = ks * 16 + g * 4;
            uint4 b0 = __ldg(bp + (nb + 0) * 32);
            uint4 b1 = __ldg(bp + (nb + 1) * 32);
            uint4 b2 = __ldg(bp + (nb + 2) * 32);
            uint4 b3 = __ldg(bp + (nb + 3) * 32);
            float (*a4)[4] = &acc[g * 4];
            mma16(a4[0], ah, b0.x, b0.y);
            mma16(a4[1], ah, b1.x, b1.y);
            mma16(a4[2], ah, b2.x, b2.y);
            mma16(a4[3], ah, b3.x, b3.y);
            mma16(a4[0], ah, b0.z, b0.w);
            mma16(a4[1], ah, b1.z, b1.w);
            mma16(a4[2], ah, b2.z, b2.w);
            mma16(a4[3], ah, b3.z, b3.w);
            mma16(a4[0], al, b0.x, b0.y);
            mma16(a4[1], al, b1.x, b1.y);
            mma16(a4[2], al, b2.x, b2.y);
            mma16(a4[3], al, b3.x, b3.y);
        }
    }
}

#define ACC_ZERO8(acc) do { \
    _Pragma("unroll") for (int _b = 0; _b < 8; _b++) \
    _Pragma("unroll") for (int _c = 0; _c < 4; _c++) acc[_b][_c] = 0.f; } while (0)

// ---------------------------------------------------------------------------
// k_prep: bf16-split packed B fragments (B[n][k] = W[k][n]).
// ---------------------------------------------------------------------------
__global__ void k_prep(const float* __restrict__ Win, const float* __restrict__ U,
                       const float* __restrict__ Wout)
{
    int i = blockIdx.x * 256 + threadIdx.x;
    if (i < 3 * 4096) {
        int w = i >> 12, r = i & 4095;
        int ks = r >> 9, ng = (r >> 5) & 15, lane = r & 31;
        int n = ng * 8 + (lane >> 2);
        int k0 = ks * 16 + (lane & 3) * 2;
        const float* W = (w == 0) ? Win : ((w == 1) ? U : Wout);
        float v00 = W[k0 * 128 + n],       v01 = W[(k0 + 1) * 128 + n];
        float v10 = W[(k0 + 8) * 128 + n], v11 = W[(k0 + 9) * 128 + n];
        float h00 = bfv(v00), h01 = bfv(v01), h10 = bfv(v10), h11 = bfv(v11);
        g_Bfrag[w][r] = make_uint4(pack_bf(h00, h01), pack_bf(h10, h11),
                                   pack_bf(v00 - h00, v01 - h01),
                                   pack_bf(v10 - h10, v11 - h11));
    }
}

// ---------------------------------------------------------------------------
// k_vocab (fused): Pb = emb@W_in + b_in; T = tanh(Pb); Q = T@W_out
// 64 rows/block; tanh restaged from acc between passes (race-safe syncs).
// ---------------------------------------------------------------------------
__global__ void __launch_bounds__(256, 3)
k_vocab(const float* __restrict__ emb, const float* __restrict__ b_in)
{
    extern __shared__ uint32_t sm[];
    uint32_t* AsH = sm;
    uint32_t* AsL = sm + 64 * KP;

    const int tid = threadIdx.x, wid = tid >> 5, lane = tid & 31;
    const int wr = wid & 3, wc = wid >> 2;
    const int row0 = blockIdx.x * 64;

    for (int i = tid; i < 2048; i += 256) {
        int row = i >> 5, q = i & 31;
        float4 v = ((const float4*)emb)[(size_t)(row0 + row) * 32 + q];
        store_k4(AsH, AsL, row, q, v);
    }
    __syncthreads();

    float acc[8][4];
    ACC_ZERO8(acc);
    gemm64(AsH, AsL, g_Bfrag[0], wr, wc, lane, acc);

    // epilogue 1: Pb, T; keep tanh in acc
#pragma unroll
    for (int h = 0; h < 2; h++) {
        const size_t node = row0 + wr * 16 + (lane >> 2) + h * 8;
#pragma unroll
        for (int nt = 0; nt < 8; nt++) {
            const int col = wc * 64 + nt * 8 + (lane & 3) * 2;
            float2 b = *(const float2*)&b_in[col];
            float p0 = acc[nt][h * 2]     + b.x;
            float p1 = acc[nt][h * 2 + 1] + b.y;
            *(float2*)&g_Pb[node * 128 + col] = make_float2(p0, p1);
            float t0 = tanhf(p0), t1 = tanhf(p1);
            *(float2*)&g_T[node * 128 + col] = make_float2(t0, t1);
            acc[nt][h * 2]     = t0;
            acc[nt][h * 2 + 1] = t1;
        }
    }
    __syncthreads();   // all warps done READING As in pass 1
#pragma unroll
    for (int h = 0; h < 2; h++) {
        const int r = wr * 16 + (lane >> 2) + h * 8;
#pragma unroll
        for (int nt = 0; nt < 8; nt++) {
            const int col = wc * 64 + nt * 8 + (lane & 3) * 2;
            float t0 = acc[nt][h * 2], t1 = acc[nt][h * 2 + 1];
            float h0 = bfv(t0), h1 = bfv(t1);
            AsH[r * KP + (col >> 1)] = pack_bf(h0, h1);
            AsL[r * KP + (col >> 1)] = pack_bf(t0 - h0, t1 - h1);
        }
    }
    __syncthreads();

    ACC_ZERO8(acc);
    gemm64(AsH, AsL, g_Bfrag[2], wr, wc, lane, acc);

#pragma unroll
    for (int h = 0; h < 2; h++) {
        const size_t node = row0 + wr * 16 + (lane >> 2) + h * 8;
#pragma unroll
        for (int nt = 0; nt < 8; nt++) {
            const int col = wc * 64 + nt * 8 + (lane & 3) * 2;
            *(float2*)&g_Q[node * 128 + col] =
                make_float2(acc[nt][h * 2], acc[nt][h * 2 + 1]);
        }
    }
}

// ---------------------------------------------------------------------------
// k_level5: h[node] = tanh(Pb[x*m]*m + (sum_c m_c*T[x_c]) @ U)  (64 rows/block)
// ---------------------------------------------------------------------------
__global__ void __launch_bounds__(256, 3)
k_level5(int s, const int* __restrict__ x, const int* __restrict__ mask,
         const int* __restrict__ children)
{
    extern __shared__ uint32_t sm[];
    uint32_t* AsH = sm;
    uint32_t* AsL = sm + 64 * KP;

    const int tid = threadIdx.x, wid = tid >> 5, lane = tid & 31;
    const int wr = wid & 3, wc = wid >> 2;
    const int row0 = blockIdx.x * 64;

    for (int i = tid; i < 2048; i += 256) {
        int row = i >> 5, f4 = i & 31;
        int node = s + row0 + row;
        float4 acc4 = make_float4(0.f, 0.f, 0.f, 0.f);
#pragma unroll
        for (int c = 0; c < 8; c++) {
            int cc = children[(size_t)node * 8 + c];
            int mm = mask[cc];
            float fm = (float)mm;
            float4 t = ((const float4*)g_T)[(size_t)(x[cc] * mm) * 32 + f4];
            acc4.x = fmaf(t.x, fm, acc4.x); acc4.y = fmaf(t.y, fm, acc4.y);
            acc4.z = fmaf(t.z, fm, acc4.z); acc4.w = fmaf(t.w, fm, acc4.w);
        }
        store_k4(AsH, AsL, row, f4, acc4);
    }
    __syncthreads();

    float acc[8][4];
    ACC_ZERO8(acc);
    gemm64(AsH, AsL, g_Bfrag[1], wr, wc, lane, acc);

#pragma unroll
    for (int h = 0; h < 2; h++) {
        const int node = s + row0 + wr * 16 + (lane >> 2) + h * 8;
        const float mf = (float)mask[node];
        const size_t xm = (size_t)(x[node] * mask[node]);
#pragma unroll
        for (int nt = 0; nt < 8; nt++) {
            const int col = wc * 64 + nt * 8 + (lane & 3) * 2;
            float2 p = *(const float2*)&g_Pb[xm * 128 + col];
            float o0 = tanhf(acc[nt][h * 2]     + p.x * mf);
            float o1 = tanhf(acc[nt][h * 2 + 1] + p.y * mf);
            *(float2*)&g_h[(size_t)node * 128 + col] = make_float2(o0, o1);
        }
    }
}

// ---------------------------------------------------------------------------
// k_out_t: out[r0 .. r0+nrows) = g_h @ W_out + b_out  (64 rows/block)
// ---------------------------------------------------------------------------
__global__ void __launch_bounds__(256, 3)
k_out_t(int r0, int nrows, const float* __restrict__ b_out, float* __restrict__ out)
{
    extern __shared__ uint32_t sm[];
    uint32_t* AsH = sm;
    uint32_t* AsL = sm + 64 * KP;

    const int tid = threadIdx.x, wid = tid >> 5, lane = tid & 31;
    const int wr = wid & 3, wc = wid >> 2;
    const int row0 = r0 + blockIdx.x * 64;
    const int e = r0 + nrows;

    for (int i = tid; i < 2048; i += 256) {
        int row = i >> 5, q = i & 31;
        int rr = row0 + row; if (rr >= e) rr = e - 1;
        float4 v = ((const float4*)g_h)[(size_t)rr * 32 + q];
        store_k4(AsH, AsL, row, q, v);
    }
    __syncthreads();

    float acc[8][4];
    ACC_ZERO8(acc);
    gemm64(AsH, AsL, g_Bfrag[2], wr, wc, lane, acc);

#pragma unroll
    for (int h = 0; h < 2; h++) {
        const int node = row0 + wr * 16 + (lane >> 2) + h * 8;
        if (node < e) {
#pragma unroll
            for (int nt = 0; nt < 8; nt++) {
                const int col = wc * 64 + nt * 8 + (lane & 3) * 2;
                float2 b = *(const float2*)&b_out[col];
                float2 o = make_float2(acc[nt][h * 2] + b.x,
                                       acc[nt][h * 2 + 1] + b.y);
                __stcs((float2*)&out[(size_t)node * 128 + col], o);
            }
        }
    }
}

// ---------------------------------------------------------------------------
// node-level FFMA body: 16 nodes per block-slot, 256 threads
// ---------------------------------------------------------------------------
__device__ __forceinline__ void nodes_body(int base, int s, int e,
                                           const int* __restrict__ x,
                                           const int* __restrict__ mask,
                                           const int* __restrict__ children,
                                           const float* __restrict__ U,
                                           float (*agg)[128])
{
    const int tid = threadIdx.x;
    const int col = tid & 127, half = tid >> 7;

#pragma unroll
    for (int g = 0; g < 8; g++) {
        const int node = base + half * 8 + g;
        const int nb = (node < e) ? node : s;
        float sum = 0.f;
#pragma unroll
        for (int c = 0; c < 8; c++)
            sum += g_h[(size_t)children[(size_t)nb * 8 + c] * 128 + col];
        agg[half * 8 + g][col] = sum;
    }
    __syncthreads();

    float acc[8];
#pragma unroll
    for (int g = 0; g < 8; g++) acc[g] = 0.f;
#pragma unroll 4
    for (int k = 0; k < 128; k++) {
        const float u = __ldg(&U[k * 128 + col]);
#pragma unroll
        for (int g = 0; g < 8; g++)
            acc[g] = fmaf(agg[half * 8 + g][k], u, acc[g]);
    }

#pragma unroll
    for (int g = 0; g < 8; g++) {
        const int node = base + half * 8 + g;
        if (node < e) {
            const float mf = (float)mask[node];
            const int xm = x[node] * mask[node];
            const float hin = g_Pb[(size_t)xm * 128 + col] * mf;
            g_h[(size_t)node * 128 + col] = tanhf(hin + acc[g]);
        }
    }
}

__global__ void __launch_bounds__(256, 4)
k_nodes(int s, int n, const int* __restrict__ x, const int* __restrict__ mask,
        const int* __restrict__ children, const float* __restrict__ U)
{
    __shared__ float agg[16][128];
    nodes_body(s + blockIdx.x * 16, s, s + n, x, mask, children, U, agg);
}

__global__ void __launch_bounds__(256, 1)
k_tail(const int* __restrict__ x, const int* __restrict__ mask,
       const int* __restrict__ children, const float* __restrict__ U)
{
    __shared__ float agg[16][128];
    const int ls[3] = {9, 1, 0};
    const int ln[3] = {64, 8, 1};
    for (int lv = 0; lv < 3; lv++) {
        const int s = ls[lv], e = s + ln[lv];
        for (int base = s; base < e; base += 16) {
            nodes_body(base, s, e, x, mask, children, U, agg);
            __syncthreads();
        }
    }
}

// ---------------------------------------------------------------------------
// k_out_leaf: out[leaf] = mask * Q[x] + b_out  (streaming stores)
// ---------------------------------------------------------------------------
__global__ void __launch_bounds__(256)
k_out_leaf(const int* __restrict__ x, const int* __restrict__ mask,
           const float* __restrict__ b_out, float* __restrict__ out)
{
    const float4 bv = ((const float4*)b_out)[threadIdx.x & 31];
    int idx = blockIdx.x * 256 + threadIdx.x;
#pragma unroll
    for (int it = 0; it < 4; it++, idx += 8192 * 256) {
        const int rr = idx >> 5, c = idx & 31;
        const int node = NINT + rr;
        const int m = mask[node];
        const int xm = x[node] * m;
        const float mf = (float)m;
        float4 q = __ldg(&((const float4*)g_Q)[(size_t)xm * 32 + c]);
        float4 o = make_float4(fmaf(q.x, mf, bv.x), fmaf(q.y, mf, bv.y),
                               fmaf(q.z, mf, bv.z), fmaf(q.w, mf, bv.w));
        __stcs(&((float4*)out)[(size_t)node * 32 + c], o);
    }
}

// ---------------------------------------------------------------------------
extern "C" void kernel_launch(void* const* d_in, const int* in_sizes, int n_in,
                              void* d_out, int out_size)
{
    const int*   x        = (const int*)  d_in[0];
    const int*   mask     = (const int*)  d_in[1];
    const int*   children = (const int*)  d_in[2];
    const float* emb      = (const float*)d_in[3];
    const float* W_in     = (const float*)d_in[4];
    const float* b_in     = (const float*)d_in[5];
    const float* U        = (const float*)d_in[6];
    const float* W_out    = (const float*)d_in[7];
    const float* b_out    = (const float*)d_in[8];
    float*       out      = (float*)d_out;
    (void)in_sizes; (void)n_in; (void)out_size;

    static cudaStream_t sA = nullptr, sB = nullptr;
    static cudaEvent_t  eT, eH5, eJ1, eJ2;
    if (!sA) {
        cudaStreamCreateWithFlags(&sA, cudaStreamNonBlocking);
        cudaStreamCreateWithFlags(&sB, cudaStreamNonBlocking);
        cudaEventCreateWithFlags(&eT,  cudaEventDisableTiming);
        cudaEventCreateWithFlags(&eH5, cudaEventDisableTiming);
        cudaEventCreateWithFlags(&eJ1, cudaEventDisableTiming);
        cudaEventCreateWithFlags(&eJ2, cudaEventDisableTiming);
    }
    cudaStream_t s0 = 0;

    k_prep<<<48, 256, 0, s0>>>(W_in, U, W_out);
    // Pb, T, Q (fused)
    k_vocab<<<500, 256, SMEM_BYTES, s0>>>(emb, b_in);
    cudaEventRecord(eT, s0);

    // side stream A: leaf outputs (needs Q only)
    cudaStreamWaitEvent(sA, eT, 0);
    k_out_leaf<<<8192, 256, 0, sA>>>(x, mask, b_out, out);
    cudaEventRecord(eJ1, sA);

    // critical path: level 5 hidden
    k_level5<<<512, 256, SMEM_BYTES, s0>>>(4681, x, mask, children);
    cudaEventRecord(eH5, s0);

    // side stream B: output GEMM for L5 rows
    cudaStreamWaitEvent(sB, eH5, 0);
    k_out_t<<<512, 256, SMEM_BYTES, sB>>>(4681, 32768, b_out, out);
    cudaEventRecord(eJ2, sB);

    // critical path: L4..L0, then output head
    k_nodes<<<256, 256, 0, s0>>>(585, 4096, x, mask, children, U); // L4
    k_nodes<<< 32, 256, 0, s0>>>( 73,  512, x, mask, children, U); // L3
    k_tail <<<  1, 256, 0, s0>>>(x, mask, children, U);            // L2..L0
    k_out_t<<<74, 256, SMEM_BYTES, s0>>>(0, 4681, b_out, out);     // out rows 0..4681

    cudaStreamWaitEvent(s0, eJ1, 0);
    cudaStreamWaitEvent(s0, eJ2, 0);
}

// round 11
// speedup vs baseline: 1.0192x; 1.0192x over previous
#include <cuda_runtime.h>
#include <cuda_bf16.h>
#include <math.h>
#include <stdint.h>

#define NINT 37449
#define NVOC 32000

// ---------------- device scratch (no allocs allowed) ----------------
static __device__ float g_Pb[(size_t)NVOC * 128]; // emb@W_in + b_in
static __device__ float g_T [(size_t)NVOC * 128]; // tanh(Pb)
static __device__ float g_Q [(size_t)NVOC * 128]; // T@W_out
static __device__ float g_h [(size_t)NINT * 128]; // hidden, internal nodes
static __device__ uint4 g_Bfrag[3][4096];         // {Win,U,Wout}: {bh0,bh1,bl0,bl1} packed bf16x2

// smem: AsH[64][68] + AsL[64][68] packed bf16x2 (hi/lo split of A)
#define KP 68
#define SMEM_BYTES (64 * KP * 4 * 2)   // 34816

__device__ __forceinline__ uint32_t pack_bf(float v0, float v1) {
    uint32_t r;
    asm("cvt.rn.bf16x2.f32 %0, %1, %2;" : "=r"(r) : "f"(v1), "f"(v0));
    return r;
}
__device__ __forceinline__ float bfv(float v) {
    return __bfloat162float(__float2bfloat16(v));
}

__device__ __forceinline__ void store_k4(uint32_t* AsH, uint32_t* AsL,
                                         int row, int f4, float4 v) {
    float h0 = bfv(v.x), h1 = bfv(v.y), h2 = bfv(v.z), h3 = bfv(v.w);
    const int o = row * KP + f4 * 2;
    AsH[o]     = pack_bf(h0, h1);
    AsH[o + 1] = pack_bf(h2, h3);
    AsL[o]     = pack_bf(v.x - h0, v.y - h1);
    AsL[o + 1] = pack_bf(v.z - h2, v.w - h3);
}

__device__ __forceinline__ void mma16(float d[4], const uint32_t a[4],
                                      uint32_t b0, uint32_t b1) {
    asm volatile(
        "mma.sync.aligned.m16n8k16.row.col.f32.bf16.bf16.f32 "
        "{%0,%1,%2,%3}, {%4,%5,%6,%7}, {%8,%9}, {%0,%1,%2,%3};"
        : "+f"(d[0]), "+f"(d[1]), "+f"(d[2]), "+f"(d[3])
        : "r"(a[0]), "r"(a[1]), "r"(a[2]), "r"(a[3]), "r"(b0), "r"(b1));
}

// 64x128x128 tile GEMM, bf16 x3 (AhBh + AhBl + AlBh), A pre-split in smem.
// Warp (wr,wc): rows wr*16..+16, cols wc*64..+64.  (R9-proven simple ordering)
__device__ __forceinline__ void gemm64(const uint32_t* __restrict__ AsH,
                                       const uint32_t* __restrict__ AsL,
                                       const uint4* __restrict__ Bf,
                                       int wr, int wc, int lane,
                                       float acc[8][4])
{
    const int rA = wr * 16 + (lane >> 2);
    const int cA = lane & 3;
#pragma unroll
    for (int ks = 0; ks < 8; ks++) {
        uint32_t ah[4], al[4];
        const int kpb = ks * 8 + cA;
        ah[0] = AsH[rA * KP + kpb];
        ah[1] = AsH[(rA + 8) * KP + kpb];
        ah[2] = AsH[rA * KP + kpb + 4];
        ah[3] = AsH[(rA + 8) * KP + kpb + 4];
        al[0] = AsL[rA * KP + kpb];
        al[1] = AsL[(rA + 8) * KP + kpb];
        al[2] = AsL[rA * KP + kpb + 4];
        al[3] = AsL[(rA + 8) * KP + kpb + 4];
#pragma unroll
        for (int nt = 0; nt < 8; nt++) {
            uint4 b = __ldg(&Bf[(ks * 16 + wc * 8 + nt) * 32 + lane]);
            mma16(acc[nt], ah, b.x, b.y);
            mma16(acc[nt], ah, b.z, b.w);
            mma16(acc[nt], al, b.x, b.y);
        }
    }
}

#define ACC_ZERO8(acc) do { \
    _Pragma("unroll") for (int _b = 0; _b < 8; _b++) \
    _Pragma("unroll") for (int _c = 0; _c < 4; _c++) acc[_b][_c] = 0.f; } while (0)

// ---------------------------------------------------------------------------
// k_prep: bf16-split packed B fragments (B[n][k] = W[k][n]).
// ---------------------------------------------------------------------------
__global__ void k_prep(const float* __restrict__ Win, const float* __restrict__ U,
                       const float* __restrict__ Wout)
{
    int i = blockIdx.x * 256 + threadIdx.x;
    if (i < 3 * 4096) {
        int w = i >> 12, r = i & 4095;
        int ks = r >> 9, ng = (r >> 5) & 15, lane = r & 31;
        int n = ng * 8 + (lane >> 2);
        int k0 = ks * 16 + (lane & 3) * 2;
        const float* W = (w == 0) ? Win : ((w == 1) ? U : Wout);
        float v00 = W[k0 * 128 + n],       v01 = W[(k0 + 1) * 128 + n];
        float v10 = W[(k0 + 8) * 128 + n], v11 = W[(k0 + 9) * 128 + n];
        float h00 = bfv(v00), h01 = bfv(v01), h10 = bfv(v10), h11 = bfv(v11);
        g_Bfrag[w][r] = make_uint4(pack_bf(h00, h01), pack_bf(h10, h11),
                                   pack_bf(v00 - h00, v01 - h01),
                                   pack_bf(v10 - h10, v11 - h11));
    }
}

// ---------------------------------------------------------------------------
// k_vocab (fused): Pb = emb@W_in + b_in; T = tanh(Pb); Q = T@W_out
// ---------------------------------------------------------------------------
__global__ void __launch_bounds__(256, 3)
k_vocab(const float* __restrict__ emb, const float* __restrict__ b_in)
{
    extern __shared__ uint32_t sm[];
    uint32_t* AsH = sm;
    uint32_t* AsL = sm + 64 * KP;

    const int tid = threadIdx.x, wid = tid >> 5, lane = tid & 31;
    const int wr = wid & 3, wc = wid >> 2;
    const int row0 = blockIdx.x * 64;

    for (int i = tid; i < 2048; i += 256) {
        int row = i >> 5, q = i & 31;
        float4 v = ((const float4*)emb)[(size_t)(row0 + row) * 32 + q];
        store_k4(AsH, AsL, row, q, v);
    }
    __syncthreads();

    float acc[8][4];
    ACC_ZERO8(acc);
    gemm64(AsH, AsL, g_Bfrag[0], wr, wc, lane, acc);

    // epilogue 1: Pb, T; keep tanh in acc
#pragma unroll
    for (int h = 0; h < 2; h++) {
        const size_t node = row0 + wr * 16 + (lane >> 2) + h * 8;
#pragma unroll
        for (int nt = 0; nt < 8; nt++) {
            const int col = wc * 64 + nt * 8 + (lane & 3) * 2;
            float2 b = *(const float2*)&b_in[col];
            float p0 = acc[nt][h * 2]     + b.x;
            float p1 = acc[nt][h * 2 + 1] + b.y;
            *(float2*)&g_Pb[node * 128 + col] = make_float2(p0, p1);
            float t0 = tanhf(p0), t1 = tanhf(p1);
            *(float2*)&g_T[node * 128 + col] = make_float2(t0, t1);
            acc[nt][h * 2]     = t0;
            acc[nt][h * 2 + 1] = t1;
        }
    }
    __syncthreads();   // all warps done READING As in pass 1
#pragma unroll
    for (int h = 0; h < 2; h++) {
        const int r = wr * 16 + (lane >> 2) + h * 8;
#pragma unroll
        for (int nt = 0; nt < 8; nt++) {
            const int col = wc * 64 + nt * 8 + (lane & 3) * 2;
            float t0 = acc[nt][h * 2], t1 = acc[nt][h * 2 + 1];
            float h0 = bfv(t0), h1 = bfv(t1);
            AsH[r * KP + (col >> 1)] = pack_bf(h0, h1);
            AsL[r * KP + (col >> 1)] = pack_bf(t0 - h0, t1 - h1);
        }
    }
    __syncthreads();

    ACC_ZERO8(acc);
    gemm64(AsH, AsL, g_Bfrag[2], wr, wc, lane, acc);

#pragma unroll
    for (int h = 0; h < 2; h++) {
        const size_t node = row0 + wr * 16 + (lane >> 2) + h * 8;
#pragma unroll
        for (int nt = 0; nt < 8; nt++) {
            const int col = wc * 64 + nt * 8 + (lane & 3) * 2;
            *(float2*)&g_Q[node * 128 + col] =
                make_float2(acc[nt][h * 2], acc[nt][h * 2 + 1]);
        }
    }
}

// ---------------------------------------------------------------------------
// k_level5: h[node] = tanh(Pb[x*m]*m + (sum_c m_c*T[x_c]) @ U)  (64 rows/block)
// Staging: 4 threads own one row; child indices loaded ONCE per thread.
// ---------------------------------------------------------------------------
__global__ void __launch_bounds__(256, 3)
k_level5(int s, const int* __restrict__ x, const int* __restrict__ mask,
         const int* __restrict__ children)
{
    extern __shared__ uint32_t sm[];
    uint32_t* AsH = sm;
    uint32_t* AsL = sm + 64 * KP;

    const int tid = threadIdx.x, wid = tid >> 5, lane = tid & 31;
    const int wr = wid & 3, wc = wid >> 2;
    const int row0 = blockIdx.x * 64;

    {
        const int row = tid >> 2, q4 = tid & 3;
        const int node = s + row0 + row;
        const float* tp[8];
        float fm[8];
#pragma unroll
        for (int c = 0; c < 8; c++) {
            const int cc = children[(size_t)node * 8 + c];
            const int mm = mask[cc];
            tp[c] = g_T + (size_t)(x[cc] * mm) * 128;
            fm[c] = (float)mm;
        }
#pragma unroll
        for (int j = 0; j < 8; j++) {
            const int f4 = j * 4 + q4;
            float4 a4 = make_float4(0.f, 0.f, 0.f, 0.f);
#pragma unroll
            for (int c = 0; c < 8; c++) {
                float4 t = *(const float4*)(tp[c] + f4 * 4);
                a4.x = fmaf(t.x, fm[c], a4.x); a4.y = fmaf(t.y, fm[c], a4.y);
                a4.z = fmaf(t.z, fm[c], a4.z); a4.w = fmaf(t.w, fm[c], a4.w);
            }
            store_k4(AsH, AsL, row, f4, a4);
        }
    }
    __syncthreads();

    float acc[8][4];
    ACC_ZERO8(acc);
    gemm64(AsH, AsL, g_Bfrag[1], wr, wc, lane, acc);

#pragma unroll
    for (int h = 0; h < 2; h++) {
        const int node = s + row0 + wr * 16 + (lane >> 2) + h * 8;
        const float mf = (float)mask[node];
        const size_t xm = (size_t)(x[node] * mask[node]);
#pragma unroll
        for (int nt = 0; nt < 8; nt++) {
            const int col = wc * 64 + nt * 8 + (lane & 3) * 2;
            float2 p = *(const float2*)&g_Pb[xm * 128 + col];
            float o0 = tanhf(acc[nt][h * 2]     + p.x * mf);
            float o1 = tanhf(acc[nt][h * 2 + 1] + p.y * mf);
            *(float2*)&g_h[(size_t)node * 128 + col] = make_float2(o0, o1);
        }
    }
}

// ---------------------------------------------------------------------------
// k_out_t: out[r0 .. r0+nrows) = g_h @ W_out + b_out  (64 rows/block)
// ---------------------------------------------------------------------------
__global__ void __launch_bounds__(256, 3)
k_out_t(int r0, int nrows, const float* __restrict__ b_out, float* __restrict__ out)
{
    extern __shared__ uint32_t sm[];
    uint32_t* AsH = sm;
    uint32_t* AsL = sm + 64 * KP;

    const int tid = threadIdx.x, wid = tid >> 5, lane = tid & 31;
    const int wr = wid & 3, wc = wid >> 2;
    const int row0 = r0 + blockIdx.x * 64;
    const int e = r0 + nrows;

    for (int i = tid; i < 2048; i += 256) {
        int row = i >> 5, q = i & 31;
        int rr = row0 + row; if (rr >= e) rr = e - 1;
        float4 v = ((const float4*)g_h)[(size_t)rr * 32 + q];
        store_k4(AsH, AsL, row, q, v);
    }
    __syncthreads();

    float acc[8][4];
    ACC_ZERO8(acc);
    gemm64(AsH, AsL, g_Bfrag[2], wr, wc, lane, acc);

#pragma unroll
    for (int h = 0; h < 2; h++) {
        const int node = row0 + wr * 16 + (lane >> 2) + h * 8;
        if (node < e) {
#pragma unroll
            for (int nt = 0; nt < 8; nt++) {
                const int col = wc * 64 + nt * 8 + (lane & 3) * 2;
                float2 b = *(const float2*)&b_out[col];
                float2 o = make_float2(acc[nt][h * 2] + b.x,
                                       acc[nt][h * 2 + 1] + b.y);
                __stcs((float2*)&out[(size_t)node * 128 + col], o);
            }
        }
    }
}

// ---------------------------------------------------------------------------
// node-level FFMA body: 16 nodes per block-slot, 256 threads
// ---------------------------------------------------------------------------
__device__ __forceinline__ void nodes_body(int base, int s, int e,
                                           const int* __restrict__ x,
                                           const int* __restrict__ mask,
                                           const int* __restrict__ children,
                                           const float* __restrict__ U,
                                           float (*agg)[128])
{
    const int tid = threadIdx.x;
    const int col = tid & 127, half = tid >> 7;

#pragma unroll
    for (int g = 0; g < 8; g++) {
        const int node = base + half * 8 + g;
        const int nb = (node < e) ? node : s;
        float sum = 0.f;
#pragma unroll
        for (int c = 0; c < 8; c++)
            sum += g_h[(size_t)children[(size_t)nb * 8 + c] * 128 + col];
        agg[half * 8 + g][col] = sum;
    }
    __syncthreads();

    float acc[8];
#pragma unroll
    for (int g = 0; g < 8; g++) acc[g] = 0.f;
#pragma unroll 4
    for (int k = 0; k < 128; k++) {
        const float u = __ldg(&U[k * 128 + col]);
#pragma unroll
        for (int g = 0; g < 8; g++)
            acc[g] = fmaf(agg[half * 8 + g][k], u, acc[g]);
    }

#pragma unroll
    for (int g = 0; g < 8; g++) {
        const int node = base + half * 8 + g;
        if (node < e) {
            const float mf = (float)mask[node];
            const int xm = x[node] * mask[node];
            const float hin = g_Pb[(size_t)xm * 128 + col] * mf;
            g_h[(size_t)node * 128 + col] = tanhf(hin + acc[g]);
        }
    }
}

__global__ void __launch_bounds__(256, 4)
k_nodes(int s, int n, const int* __restrict__ x, const int* __restrict__ mask,
        const int* __restrict__ children, const float* __restrict__ U)
{
    __shared__ float agg[16][128];
    nodes_body(s + blockIdx.x * 16, s, s + n, x, mask, children, U, agg);
}

__global__ void __launch_bounds__(256, 1)
k_tail(const int* __restrict__ x, const int* __restrict__ mask,
       const int* __restrict__ children, const float* __restrict__ U)
{
    __shared__ float agg[16][128];
    const int ls[3] = {9, 1, 0};
    const int ln[3] = {64, 8, 1};
    for (int lv = 0; lv < 3; lv++) {
        const int s = ls[lv], e = s + ln[lv];
        for (int base = s; base < e; base += 16) {
            nodes_body(base, s, e, x, mask, children, U, agg);
            __syncthreads();
        }
    }
}

// ---------------------------------------------------------------------------
// k_out_leaf: out[leaf] = mask * Q[x] + b_out  (streaming stores)
// ---------------------------------------------------------------------------
__global__ void __launch_bounds__(256)
k_out_leaf(const int* __restrict__ x, const int* __restrict__ mask,
           const float* __restrict__ b_out, float* __restrict__ out)
{
    const float4 bv = ((const float4*)b_out)[threadIdx.x & 31];
    int idx = blockIdx.x * 256 + threadIdx.x;
#pragma unroll
    for (int it = 0; it < 4; it++, idx += 8192 * 256) {
        const int rr = idx >> 5, c = idx & 31;
        const int node = NINT + rr;
        const int m = mask[node];
        const int xm = x[node] * m;
        const float mf = (float)m;
        float4 q = __ldg(&((const float4*)g_Q)[(size_t)xm * 32 + c]);
        float4 o = make_float4(fmaf(q.x, mf, bv.x), fmaf(q.y, mf, bv.y),
                               fmaf(q.z, mf, bv.z), fmaf(q.w, mf, bv.w));
        __stcs(&((float4*)out)[(size_t)node * 32 + c], o);
    }
}

// ---------------------------------------------------------------------------
extern "C" void kernel_launch(void* const* d_in, const int* in_sizes, int n_in,
                              void* d_out, int out_size)
{
    const int*   x        = (const int*)  d_in[0];
    const int*   mask     = (const int*)  d_in[1];
    const int*   children = (const int*)  d_in[2];
    const float* emb      = (const float*)d_in[3];
    const float* W_in     = (const float*)d_in[4];
    const float* b_in     = (const float*)d_in[5];
    const float* U        = (const float*)d_in[6];
    const float* W_out    = (const float*)d_in[7];
    const float* b_out    = (const float*)d_in[8];
    float*       out      = (float*)d_out;
    (void)in_sizes; (void)n_in; (void)out_size;

    static cudaStream_t sA = nullptr, sB = nullptr;
    static cudaEvent_t  eT, eH5, eJ1, eJ2;
    if (!sA) {
        cudaStreamCreateWithFlags(&sA, cudaStreamNonBlocking);
        cudaStreamCreateWithFlags(&sB, cudaStreamNonBlocking);
        cudaEventCreateWithFlags(&eT,  cudaEventDisableTiming);
        cudaEventCreateWithFlags(&eH5, cudaEventDisableTiming);
        cudaEventCreateWithFlags(&eJ1, cudaEventDisableTiming);
        cudaEventCreateWithFlags(&eJ2, cudaEventDisableTiming);
    }
    cudaStream_t s0 = 0;

    k_prep<<<48, 256, 0, s0>>>(W_in, U, W_out);
    // Pb, T, Q (fused)
    k_vocab<<<500, 256, SMEM_BYTES, s0>>>(emb, b_in);
    cudaEventRecord(eT, s0);

    // side stream A: leaf outputs (needs Q only)
    cudaStreamWaitEvent(sA, eT, 0);
    k_out_leaf<<<8192, 256, 0, sA>>>(x, mask, b_out, out);
    cudaEventRecord(eJ1, sA);

    // critical path: level 5 hidden
    k_level5<<<512, 256, SMEM_BYTES, s0>>>(4681, x, mask, children);
    cudaEventRecord(eH5, s0);

    // side stream B: output GEMM for L5 rows
    cudaStreamWaitEvent(sB, eH5, 0);
    k_out_t<<<512, 256, SMEM_BYTES, sB>>>(4681, 32768, b_out, out);
    cudaEventRecord(eJ2, sB);

    // critical path: L4..L0, then output head
    k_nodes<<<256, 256, 0, s0>>>(585, 4096, x, mask, children, U); // L4
    k_nodes<<< 32, 256, 0, s0>>>( 73,  512, x, mask, children, U); // L3
    k_tail <<<  1, 256, 0, s0>>>(x, mask, children, U);            // L2..L0
    k_out_t<<<74, 256, SMEM_BYTES, s0>>>(0, 4681, b_out, out);     // out rows 0..4681

    cudaStreamWaitEvent(s0, eJ1, 0);
    cudaStreamWaitEvent(s0, eJ2, 0);
}

// round 12
// speedup vs baseline: 1.1261x; 1.1049x over previous
#include <cuda_runtime.h>
#include <cuda_bf16.h>
#include <cuda_fp16.h>
#include <math.h>
#include <stdint.h>

#define NINT 37449
#define NVOC 32000

// ---------------- device scratch (no allocs allowed) ----------------
static __device__ __half g_Pbh[(size_t)NVOC * 128]; // emb@W_in + b_in   (fp16)
static __device__ __half g_Th [(size_t)NVOC * 128]; // tanh(Pb)          (fp16)
static __device__ __half g_Qh [(size_t)NVOC * 128]; // T@W_out           (fp16)
static __device__ float  g_h  [(size_t)NINT * 128]; // hidden, internal nodes
static __device__ uint4  g_Bfrag[3][4096];          // {Win,U,Wout}: {bh0,bh1,bl0,bl1} bf16x2

// smem: AsH[64][68] + AsL[64][68] packed bf16x2 (hi/lo split of A)
#define KP 68
#define SMEM_BYTES (64 * KP * 4 * 2)   // 34816

__device__ __forceinline__ uint32_t pack_bf(float v0, float v1) {
    uint32_t r;
    asm("cvt.rn.bf16x2.f32 %0, %1, %2;" : "=r"(r) : "f"(v1), "f"(v0));
    return r;
}
__device__ __forceinline__ float bfv(float v) {
    return __bfloat162float(__float2bfloat16(v));
}

__device__ __forceinline__ void store_k4(uint32_t* AsH, uint32_t* AsL,
                                         int row, int f4, float4 v) {
    float h0 = bfv(v.x), h1 = bfv(v.y), h2 = bfv(v.z), h3 = bfv(v.w);
    const int o = row * KP + f4 * 2;
    AsH[o]     = pack_bf(h0, h1);
    AsH[o + 1] = pack_bf(h2, h3);
    AsL[o]     = pack_bf(v.x - h0, v.y - h1);
    AsL[o + 1] = pack_bf(v.z - h2, v.w - h3);
}

__device__ __forceinline__ void mma16(float d[4], const uint32_t a[4],
                                      uint32_t b0, uint32_t b1) {
    asm volatile(
        "mma.sync.aligned.m16n8k16.row.col.f32.bf16.bf16.f32 "
        "{%0,%1,%2,%3}, {%4,%5,%6,%7}, {%8,%9}, {%0,%1,%2,%3};"
        : "+f"(d[0]), "+f"(d[1]), "+f"(d[2]), "+f"(d[3])
        : "r"(a[0]), "r"(a[1]), "r"(a[2]), "r"(a[3]), "r"(b0), "r"(b1));
}

// 64x128x128 tile GEMM, bf16 x3 (AhBh + AhBl + AlBh), A pre-split in smem.
// Warp (wr,wc): rows wr*16..+16, cols wc*64..+64.  (R9/R11-proven ordering)
__device__ __forceinline__ void gemm64(const uint32_t* __restrict__ AsH,
                                       const uint32_t* __restrict__ AsL,
                                       const uint4* __restrict__ Bf,
                                       int wr, int wc, int lane,
                                       float acc[8][4])
{
    const int rA = wr * 16 + (lane >> 2);
    const int cA = lane & 3;
#pragma unroll
    for (int ks = 0; ks < 8; ks++) {
        uint32_t ah[4], al[4];
        const int kpb = ks * 8 + cA;
        ah[0] = AsH[rA * KP + kpb];
        ah[1] = AsH[(rA + 8) * KP + kpb];
        ah[2] = AsH[rA * KP + kpb + 4];
        ah[3] = AsH[(rA + 8) * KP + kpb + 4];
        al[0] = AsL[rA * KP + kpb];
        al[1] = AsL[(rA + 8) * KP + kpb];
        al[2] = AsL[rA * KP + kpb + 4];
        al[3] = AsL[(rA + 8) * KP + kpb + 4];
#pragma unroll
        for (int nt = 0; nt < 8; nt++) {
            uint4 b = __ldg(&Bf[(ks * 16 + wc * 8 + nt) * 32 + lane]);
            mma16(acc[nt], ah, b.x, b.y);
            mma16(acc[nt], ah, b.z, b.w);
            mma16(acc[nt], al, b.x, b.y);
        }
    }
}

#define ACC_ZERO8(acc) do { \
    _Pragma("unroll") for (int _b = 0; _b < 8; _b++) \
    _Pragma("unroll") for (int _c = 0; _c < 4; _c++) acc[_b][_c] = 0.f; } while (0)

// ---------------------------------------------------------------------------
// k_prep: bf16-split packed B fragments (B[n][k] = W[k][n]).
// ---------------------------------------------------------------------------
__global__ void k_prep(const float* __restrict__ Win, const float* __restrict__ U,
                       const float* __restrict__ Wout)
{
    int i = blockIdx.x * 256 + threadIdx.x;
    if (i < 3 * 4096) {
        int w = i >> 12, r = i & 4095;
        int ks = r >> 9, ng = (r >> 5) & 15, lane = r & 31;
        int n = ng * 8 + (lane >> 2);
        int k0 = ks * 16 + (lane & 3) * 2;
        const float* W = (w == 0) ? Win : ((w == 1) ? U : Wout);
        float v00 = W[k0 * 128 + n],       v01 = W[(k0 + 1) * 128 + n];
        float v10 = W[(k0 + 8) * 128 + n], v11 = W[(k0 + 9) * 128 + n];
        float h00 = bfv(v00), h01 = bfv(v01), h10 = bfv(v10), h11 = bfv(v11);
        g_Bfrag[w][r] = make_uint4(pack_bf(h00, h01), pack_bf(h10, h11),
                                   pack_bf(v00 - h00, v01 - h01),
                                   pack_bf(v10 - h10, v11 - h11));
    }
}

// ---------------------------------------------------------------------------
// k_vocab (fused): Pb = emb@W_in + b_in; T = tanh(Pb); Q = T@W_out
// Pb/T/Q stored as fp16 tables (gather traffic halved).
// ---------------------------------------------------------------------------
__global__ void __launch_bounds__(256, 3)
k_vocab(const float* __restrict__ emb, const float* __restrict__ b_in)
{
    extern __shared__ uint32_t sm[];
    uint32_t* AsH = sm;
    uint32_t* AsL = sm + 64 * KP;

    const int tid = threadIdx.x, wid = tid >> 5, lane = tid & 31;
    const int wr = wid & 3, wc = wid >> 2;
    const int row0 = blockIdx.x * 64;

    for (int i = tid; i < 2048; i += 256) {
        int row = i >> 5, q = i & 31;
        float4 v = ((const float4*)emb)[(size_t)(row0 + row) * 32 + q];
        store_k4(AsH, AsL, row, q, v);
    }
    __syncthreads();

    float acc[8][4];
    ACC_ZERO8(acc);
    gemm64(AsH, AsL, g_Bfrag[0], wr, wc, lane, acc);

    // epilogue 1: Pb(fp16), T(fp16); keep tanh in acc
#pragma unroll
    for (int h = 0; h < 2; h++) {
        const size_t node = row0 + wr * 16 + (lane >> 2) + h * 8;
#pragma unroll
        for (int nt = 0; nt < 8; nt++) {
            const int col = wc * 64 + nt * 8 + (lane & 3) * 2;
            float2 b = *(const float2*)&b_in[col];
            float p0 = acc[nt][h * 2]     + b.x;
            float p1 = acc[nt][h * 2 + 1] + b.y;
            *(__half2*)&g_Pbh[node * 128 + col] = __floats2half2_rn(p0, p1);
            float t0 = tanhf(p0), t1 = tanhf(p1);
            *(__half2*)&g_Th[node * 128 + col] = __floats2half2_rn(t0, t1);
            acc[nt][h * 2]     = t0;
            acc[nt][h * 2 + 1] = t1;
        }
    }
    __syncthreads();   // all warps done READING As in pass 1
#pragma unroll
    for (int h = 0; h < 2; h++) {
        const int r = wr * 16 + (lane >> 2) + h * 8;
#pragma unroll
        for (int nt = 0; nt < 8; nt++) {
            const int col = wc * 64 + nt * 8 + (lane & 3) * 2;
            float t0 = acc[nt][h * 2], t1 = acc[nt][h * 2 + 1];
            float h0 = bfv(t0), h1 = bfv(t1);
            AsH[r * KP + (col >> 1)] = pack_bf(h0, h1);
            AsL[r * KP + (col >> 1)] = pack_bf(t0 - h0, t1 - h1);
        }
    }
    __syncthreads();

    ACC_ZERO8(acc);
    gemm64(AsH, AsL, g_Bfrag[2], wr, wc, lane, acc);

#pragma unroll
    for (int h = 0; h < 2; h++) {
        const size_t node = row0 + wr * 16 + (lane >> 2) + h * 8;
#pragma unroll
        for (int nt = 0; nt < 8; nt++) {
            const int col = wc * 64 + nt * 8 + (lane & 3) * 2;
            *(__half2*)&g_Qh[node * 128 + col] =
                __floats2half2_rn(acc[nt][h * 2], acc[nt][h * 2 + 1]);
        }
    }
}

// ---------------------------------------------------------------------------
// k_level5: h[node] = tanh(Pb[x*m]*m + (sum_c m_c*T[x_c]) @ U)  (64 rows/block)
// Gathers fp16 T rows (256 B each). 4 threads per row; indices loaded once.
// ---------------------------------------------------------------------------
__global__ void __launch_bounds__(256, 3)
k_level5(int s, const int* __restrict__ x, const int* __restrict__ mask,
         const int* __restrict__ children)
{
    extern __shared__ uint32_t sm[];
    uint32_t* AsH = sm;
    uint32_t* AsL = sm + 64 * KP;

    const int tid = threadIdx.x, wid = tid >> 5, lane = tid & 31;
    const int wr = wid & 3, wc = wid >> 2;
    const int row0 = blockIdx.x * 64;

    {
        const int row = tid >> 2, q4 = tid & 3;
        const int node = s + row0 + row;
        const __half* tp[8];
        float fm[8];
#pragma unroll
        for (int c = 0; c < 8; c++) {
            const int cc = children[(size_t)node * 8 + c];
            const int mm = mask[cc];
            tp[c] = g_Th + (size_t)(x[cc] * mm) * 128;
            fm[c] = (float)mm;
        }
#pragma unroll
        for (int j = 0; j < 4; j++) {
            const int cid = j * 4 + q4;      // 16-byte chunk = 8 halves
            float v[8];
#pragma unroll
            for (int k = 0; k < 8; k++) v[k] = 0.f;
#pragma unroll
            for (int c = 0; c < 8; c++) {
                uint4 w = *(const uint4*)(tp[c] + cid * 8);
                float2 f0 = __half22float2(*(const __half2*)&w.x);
                float2 f1 = __half22float2(*(const __half2*)&w.y);
                float2 f2 = __half22float2(*(const __half2*)&w.z);
                float2 f3 = __half22float2(*(const __half2*)&w.w);
                v[0] = fmaf(f0.x, fm[c], v[0]); v[1] = fmaf(f0.y, fm[c], v[1]);
                v[2] = fmaf(f1.x, fm[c], v[2]); v[3] = fmaf(f1.y, fm[c], v[3]);
                v[4] = fmaf(f2.x, fm[c], v[4]); v[5] = fmaf(f2.y, fm[c], v[5]);
                v[6] = fmaf(f3.x, fm[c], v[6]); v[7] = fmaf(f3.y, fm[c], v[7]);
            }
            store_k4(AsH, AsL, row, cid * 2,     make_float4(v[0], v[1], v[2], v[3]));
            store_k4(AsH, AsL, row, cid * 2 + 1, make_float4(v[4], v[5], v[6], v[7]));
        }
    }
    __syncthreads();

    float acc[8][4];
    ACC_ZERO8(acc);
    gemm64(AsH, AsL, g_Bfrag[1], wr, wc, lane, acc);

#pragma unroll
    for (int h = 0; h < 2; h++) {
        const int node = s + row0 + wr * 16 + (lane >> 2) + h * 8;
        const float mf = (float)mask[node];
        const size_t xm = (size_t)(x[node] * mask[node]);
#pragma unroll
        for (int nt = 0; nt < 8; nt++) {
            const int col = wc * 64 + nt * 8 + (lane & 3) * 2;
            float2 p = __half22float2(*(const __half2*)&g_Pbh[xm * 128 + col]);
            float o0 = tanhf(acc[nt][h * 2]     + p.x * mf);
            float o1 = tanhf(acc[nt][h * 2 + 1] + p.y * mf);
            *(float2*)&g_h[(size_t)node * 128 + col] = make_float2(o0, o1);
        }
    }
}

// ---------------------------------------------------------------------------
// k_out_t: out[r0 .. r0+nrows) = g_h @ W_out + b_out  (64 rows/block)
// ---------------------------------------------------------------------------
__global__ void __launch_bounds__(256, 3)
k_out_t(int r0, int nrows, const float* __restrict__ b_out, float* __restrict__ out)
{
    extern __shared__ uint32_t sm[];
    uint32_t* AsH = sm;
    uint32_t* AsL = sm + 64 * KP;

    const int tid = threadIdx.x, wid = tid >> 5, lane = tid & 31;
    const int wr = wid & 3, wc = wid >> 2;
    const int row0 = r0 + blockIdx.x * 64;
    const int e = r0 + nrows;

    for (int i = tid; i < 2048; i += 256) {
        int row = i >> 5, q = i & 31;
        int rr = row0 + row; if (rr >= e) rr = e - 1;
        float4 v = ((const float4*)g_h)[(size_t)rr * 32 + q];
        store_k4(AsH, AsL, row, q, v);
    }
    __syncthreads();

    float acc[8][4];
    ACC_ZERO8(acc);
    gemm64(AsH, AsL, g_Bfrag[2], wr, wc, lane, acc);

#pragma unroll
    for (int h = 0; h < 2; h++) {
        const int node = row0 + wr * 16 + (lane >> 2) + h * 8;
        if (node < e) {
#pragma unroll
            for (int nt = 0; nt < 8; nt++) {
                const int col = wc * 64 + nt * 8 + (lane & 3) * 2;
                float2 b = *(const float2*)&b_out[col];
                float2 o = make_float2(acc[nt][h * 2] + b.x,
                                       acc[nt][h * 2 + 1] + b.y);
                __stcs((float2*)&out[(size_t)node * 128 + col], o);
            }
        }
    }
}

// ---------------------------------------------------------------------------
// node-level FFMA body: 16 nodes per block-slot, 256 threads
// ---------------------------------------------------------------------------
__device__ __forceinline__ void nodes_body(int base, int s, int e,
                                           const int* __restrict__ x,
                                           const int* __restrict__ mask,
                                           const int* __restrict__ children,
                                           const float* __restrict__ U,
                                           float (*agg)[128])
{
    const int tid = threadIdx.x;
    const int col = tid & 127, half = tid >> 7;

#pragma unroll
    for (int g = 0; g < 8; g++) {
        const int node = base + half * 8 + g;
        const int nb = (node < e) ? node : s;
        float sum = 0.f;
#pragma unroll
        for (int c = 0; c < 8; c++)
            sum += g_h[(size_t)children[(size_t)nb * 8 + c] * 128 + col];
        agg[half * 8 + g][col] = sum;
    }
    __syncthreads();

    float acc[8];
#pragma unroll
    for (int g = 0; g < 8; g++) acc[g] = 0.f;
#pragma unroll 4
    for (int k = 0; k < 128; k++) {
        const float u = __ldg(&U[k * 128 + col]);
#pragma unroll
        for (int g = 0; g < 8; g++)
            acc[g] = fmaf(agg[half * 8 + g][k], u, acc[g]);
    }

#pragma unroll
    for (int g = 0; g < 8; g++) {
        const int node = base + half * 8 + g;
        if (node < e) {
            const float mf = (float)mask[node];
            const int xm = x[node] * mask[node];
            const float hin = __half2float(g_Pbh[(size_t)xm * 128 + col]) * mf;
            g_h[(size_t)node * 128 + col] = tanhf(hin + acc[g]);
        }
    }
}

__global__ void __launch_bounds__(256, 4)
k_nodes(int s, int n, const int* __restrict__ x, const int* __restrict__ mask,
        const int* __restrict__ children, const float* __restrict__ U)
{
    __shared__ float agg[16][128];
    nodes_body(s + blockIdx.x * 16, s, s + n, x, mask, children, U, agg);
}

__global__ void __launch_bounds__(256, 1)
k_tail(const int* __restrict__ x, const int* __restrict__ mask,
       const int* __restrict__ children, const float* __restrict__ U)
{
    __shared__ float agg[16][128];
    const int ls[3] = {9, 1, 0};
    const int ln[3] = {64, 8, 1};
    for (int lv = 0; lv < 3; lv++) {
        const int s = ls[lv], e = s + ln[lv];
        for (int base = s; base < e; base += 16) {
            nodes_body(base, s, e, x, mask, children, U, agg);
            __syncthreads();
        }
    }
}

// ---------------------------------------------------------------------------
// k_out_leaf: out[leaf] = mask * Q[x] + b_out   (fp16 Q gather, streaming st)
// ---------------------------------------------------------------------------
__global__ void __launch_bounds__(256)
k_out_leaf(const int* __restrict__ x, const int* __restrict__ mask,
           const float* __restrict__ b_out, float* __restrict__ out)
{
    const float4 bv = ((const float4*)b_out)[threadIdx.x & 31];
    int idx = blockIdx.x * 256 + threadIdx.x;
#pragma unroll
    for (int it = 0; it < 4; it++, idx += 8192 * 256) {
        const int rr = idx >> 5, c = idx & 31;
        const int node = NINT + rr;
        const int m = mask[node];
        const int xm = x[node] * m;
        const float mf = (float)m;
        uint2 qw = *(const uint2*)(g_Qh + (size_t)xm * 128 + c * 4);
        float2 q0 = __half22float2(*(const __half2*)&qw.x);
        float2 q1 = __half22float2(*(const __half2*)&qw.y);
        float4 o = make_float4(fmaf(q0.x, mf, bv.x), fmaf(q0.y, mf, bv.y),
                               fmaf(q1.x, mf, bv.z), fmaf(q1.y, mf, bv.w));
        __stcs(&((float4*)out)[(size_t)node * 32 + c], o);
    }
}

// ---------------------------------------------------------------------------
extern "C" void kernel_launch(void* const* d_in, const int* in_sizes, int n_in,
                              void* d_out, int out_size)
{
    const int*   x        = (const int*)  d_in[0];
    const int*   mask     = (const int*)  d_in[1];
    const int*   children = (const int*)  d_in[2];
    const float* emb      = (const float*)d_in[3];
    const float* W_in     = (const float*)d_in[4];
    const float* b_in     = (const float*)d_in[5];
    const float* U        = (const float*)d_in[6];
    const float* W_out    = (const float*)d_in[7];
    const float* b_out    = (const float*)d_in[8];
    float*       out      = (float*)d_out;
    (void)in_sizes; (void)n_in; (void)out_size;

    static cudaStream_t sA = nullptr, sB = nullptr;
    static cudaEvent_t  eT, eH5, eJ1, eJ2;
    if (!sA) {
        cudaStreamCreateWithFlags(&sA, cudaStreamNonBlocking);
        cudaStreamCreateWithFlags(&sB, cudaStreamNonBlocking);
        cudaEventCreateWithFlags(&eT,  cudaEventDisableTiming);
        cudaEventCreateWithFlags(&eH5, cudaEventDisableTiming);
        cudaEventCreateWithFlags(&eJ1, cudaEventDisableTiming);
        cudaEventCreateWithFlags(&eJ2, cudaEventDisableTiming);
    }
    cudaStream_t s0 = 0;

    k_prep<<<48, 256, 0, s0>>>(W_in, U, W_out);
    // Pb, T, Q (fused, fp16 tables)
    k_vocab<<<500, 256, SMEM_BYTES, s0>>>(emb, b_in);
    cudaEventRecord(eT, s0);

    // side stream A: leaf outputs (needs Q only)
    cudaStreamWaitEvent(sA, eT, 0);
    k_out_leaf<<<8192, 256, 0, sA>>>(x, mask, b_out, out);
    cudaEventRecord(eJ1, sA);

    // critical path: level 5 hidden
    k_level5<<<512, 256, SMEM_BYTES, s0>>>(4681, x, mask, children);
    cudaEventRecord(eH5, s0);

    // side stream B: output GEMM for L5 rows
    cudaStreamWaitEvent(sB, eH5, 0);
    k_out_t<<<512, 256, SMEM_BYTES, sB>>>(4681, 32768, b_out, out);
    cudaEventRecord(eJ2, sB);

    // critical path: L4..L0, then output head
    k_nodes<<<256, 256, 0, s0>>>(585, 4096, x, mask, children, U); // L4
    k_nodes<<< 32, 256, 0, s0>>>( 73,  512, x, mask, children, U); // L3
    k_tail <<<  1, 256, 0, s0>>>(x, mask, children, U);            // L2..L0
    k_out_t<<<74, 256, SMEM_BYTES, s0>>>(0, 4681, b_out, out);     // out rows 0..4681

    cudaStreamWaitEvent(s0, eJ1, 0);
    cudaStreamWaitEvent(s0, eJ2, 0);
}

// round 13
// speedup vs baseline: 1.2391x; 1.1003x over previous
#include <cuda_runtime.h>
#include <cuda_fp16.h>
#include <math.h>
#include <stdint.h>

#define NINT 37449
#define NVOC 32000

// ---------------- device scratch (no allocs allowed) ----------------
static __device__ __half g_Pbh[(size_t)NVOC * 128]; // emb@W_in + b_in   (fp16)
static __device__ __half g_Th [(size_t)NVOC * 128]; // tanh(Pb)          (fp16)
static __device__ __half g_Qh [(size_t)NVOC * 128]; // T@W_out           (fp16)
static __device__ __half g_hh [(size_t)NINT * 128]; // hidden, internal  (fp16)
static __device__ uint4  g_Bfrag[3][4096];          // {Win,U,Wout}: {bh0,bh1,bl0,bl1} fp16x2

// smem: AsH[64][68] packed fp16x2 (single-precision-A; B carries the split)
#define KP 68
#define SMEM_BYTES (64 * KP * 4)   // 17408

__device__ __forceinline__ uint32_t pack_h2(float v0, float v1) {
    __half2 h = __floats2half2_rn(v0, v1);
    return *(uint32_t*)&h;
}

__device__ __forceinline__ void store_k4h(uint32_t* AsH, int row, int f4, float4 v) {
    const int o = row * KP + f4 * 2;
    AsH[o]     = pack_h2(v.x, v.y);
    AsH[o + 1] = pack_h2(v.z, v.w);
}

__device__ __forceinline__ void mma16h(float d[4], const uint32_t a[4],
                                       uint32_t b0, uint32_t b1) {
    asm volatile(
        "mma.sync.aligned.m16n8k16.row.col.f32.f16.f16.f32 "
        "{%0,%1,%2,%3}, {%4,%5,%6,%7}, {%8,%9}, {%0,%1,%2,%3};"
        : "+f"(d[0]), "+f"(d[1]), "+f"(d[2]), "+f"(d[3])
        : "r"(a[0]), "r"(a[1]), "r"(a[2]), "r"(a[3]), "r"(b0), "r"(b1));
}

// 64x128x128 tile GEMM, fp16: single A x (Bhi + Blo). 2 MMAs per (ks,nt).
// Warp (wr,wc): rows wr*16..+16, cols wc*64..+64.
__device__ __forceinline__ void gemm64h(const uint32_t* __restrict__ AsH,
                                        const uint4* __restrict__ Bf,
                                        int wr, int wc, int lane,
                                        float acc[8][4])
{
    const int rA = wr * 16 + (lane >> 2);
    const int cA = lane & 3;
#pragma unroll
    for (int ks = 0; ks < 8; ks++) {
        uint32_t ah[4];
        const int kpb = ks * 8 + cA;
        ah[0] = AsH[rA * KP + kpb];
        ah[1] = AsH[(rA + 8) * KP + kpb];
        ah[2] = AsH[rA * KP + kpb + 4];
        ah[3] = AsH[(rA + 8) * KP + kpb + 4];
#pragma unroll
        for (int nt = 0; nt < 8; nt++) {
            uint4 b = __ldg(&Bf[(ks * 16 + wc * 8 + nt) * 32 + lane]);
            mma16h(acc[nt], ah, b.x, b.y);   // A * B_hi
            mma16h(acc[nt], ah, b.z, b.w);   // A * B_lo
        }
    }
}

#define ACC_ZERO8(acc) do { \
    _Pragma("unroll") for (int _b = 0; _b < 8; _b++) \
    _Pragma("unroll") for (int _c = 0; _c < 4; _c++) acc[_b][_c] = 0.f; } while (0)

// ---------------------------------------------------------------------------
// k_prep: fp16-split packed B fragments (B[n][k] = W[k][n]).
// ---------------------------------------------------------------------------
__global__ void k_prep(const float* __restrict__ Win, const float* __restrict__ U,
                       const float* __restrict__ Wout)
{
    int i = blockIdx.x * 256 + threadIdx.x;
    if (i < 3 * 4096) {
        int w = i >> 12, r = i & 4095;
        int ks = r >> 9, ng = (r >> 5) & 15, lane = r & 31;
        int n = ng * 8 + (lane >> 2);
        int k0 = ks * 16 + (lane & 3) * 2;
        const float* W = (w == 0) ? Win : ((w == 1) ? U : Wout);
        float v00 = W[k0 * 128 + n],       v01 = W[(k0 + 1) * 128 + n];
        float v10 = W[(k0 + 8) * 128 + n], v11 = W[(k0 + 9) * 128 + n];
        float h00 = __half2float(__float2half_rn(v00));
        float h01 = __half2float(__float2half_rn(v01));
        float h10 = __half2float(__float2half_rn(v10));
        float h11 = __half2float(__float2half_rn(v11));
        g_Bfrag[w][r] = make_uint4(pack_h2(h00, h01), pack_h2(h10, h11),
                                   pack_h2(v00 - h00, v01 - h01),
                                   pack_h2(v10 - h10, v11 - h11));
    }
}

// ---------------------------------------------------------------------------
// k_vocab (fused): Pb = emb@W_in + b_in; T = tanh(Pb); Q = T@W_out
// ---------------------------------------------------------------------------
__global__ void __launch_bounds__(256, 3)
k_vocab(const float* __restrict__ emb, const float* __restrict__ b_in)
{
    extern __shared__ uint32_t sm[];
    uint32_t* AsH = sm;

    const int tid = threadIdx.x, wid = tid >> 5, lane = tid & 31;
    const int wr = wid & 3, wc = wid >> 2;
    const int row0 = blockIdx.x * 64;

    for (int i = tid; i < 2048; i += 256) {
        int row = i >> 5, q = i & 31;
        float4 v = ((const float4*)emb)[(size_t)(row0 + row) * 32 + q];
        store_k4h(AsH, row, q, v);
    }
    __syncthreads();

    float acc[8][4];
    ACC_ZERO8(acc);
    gemm64h(AsH, g_Bfrag[0], wr, wc, lane, acc);

    // epilogue 1: Pb(fp16), T(fp16); keep tanh in acc
#pragma unroll
    for (int h = 0; h < 2; h++) {
        const size_t node = row0 + wr * 16 + (lane >> 2) + h * 8;
#pragma unroll
        for (int nt = 0; nt < 8; nt++) {
            const int col = wc * 64 + nt * 8 + (lane & 3) * 2;
            float2 b = *(const float2*)&b_in[col];
            float p0 = acc[nt][h * 2]     + b.x;
            float p1 = acc[nt][h * 2 + 1] + b.y;
            *(__half2*)&g_Pbh[node * 128 + col] = __floats2half2_rn(p0, p1);
            float t0 = tanhf(p0), t1 = tanhf(p1);
            *(__half2*)&g_Th[node * 128 + col] = __floats2half2_rn(t0, t1);
            acc[nt][h * 2]     = t0;
            acc[nt][h * 2 + 1] = t1;
        }
    }
    __syncthreads();   // all warps done READING As in pass 1
#pragma unroll
    for (int h = 0; h < 2; h++) {
        const int r = wr * 16 + (lane >> 2) + h * 8;
#pragma unroll
        for (int nt = 0; nt < 8; nt++) {
            const int col = wc * 64 + nt * 8 + (lane & 3) * 2;
            AsH[r * KP + (col >> 1)] = pack_h2(acc[nt][h * 2], acc[nt][h * 2 + 1]);
        }
    }
    __syncthreads();

    ACC_ZERO8(acc);
    gemm64h(AsH, g_Bfrag[2], wr, wc, lane, acc);

#pragma unroll
    for (int h = 0; h < 2; h++) {
        const size_t node = row0 + wr * 16 + (lane >> 2) + h * 8;
#pragma unroll
        for (int nt = 0; nt < 8; nt++) {
            const int col = wc * 64 + nt * 8 + (lane & 3) * 2;
            *(__half2*)&g_Qh[node * 128 + col] =
                __floats2half2_rn(acc[nt][h * 2], acc[nt][h * 2 + 1]);
        }
    }
}

// ---------------------------------------------------------------------------
// k_level5: h[node] = tanh(Pb[x*m]*m + (sum_c m_c*T[x_c]) @ U)  (64 rows/block)
// ---------------------------------------------------------------------------
__global__ void __launch_bounds__(256, 3)
k_level5(int s, const int* __restrict__ x, const int* __restrict__ mask,
         const int* __restrict__ children)
{
    extern __shared__ uint32_t sm[];
    uint32_t* AsH = sm;

    const int tid = threadIdx.x, wid = tid >> 5, lane = tid & 31;
    const int wr = wid & 3, wc = wid >> 2;
    const int row0 = blockIdx.x * 64;

    {
        const int row = tid >> 2, q4 = tid & 3;
        const int node = s + row0 + row;
        const __half* tp[8];
        float fm[8];
#pragma unroll
        for (int c = 0; c < 8; c++) {
            const int cc = children[(size_t)node * 8 + c];
            const int mm = mask[cc];
            tp[c] = g_Th + (size_t)(x[cc] * mm) * 128;
            fm[c] = (float)mm;
        }
#pragma unroll
        for (int j = 0; j < 4; j++) {
            const int cid = j * 4 + q4;      // 16-byte chunk = 8 halves
            float v[8];
#pragma unroll
            for (int k = 0; k < 8; k++) v[k] = 0.f;
#pragma unroll
            for (int c = 0; c < 8; c++) {
                uint4 w = *(const uint4*)(tp[c] + cid * 8);
                float2 f0 = __half22float2(*(const __half2*)&w.x);
                float2 f1 = __half22float2(*(const __half2*)&w.y);
                float2 f2 = __half22float2(*(const __half2*)&w.z);
                float2 f3 = __half22float2(*(const __half2*)&w.w);
                v[0] = fmaf(f0.x, fm[c], v[0]); v[1] = fmaf(f0.y, fm[c], v[1]);
                v[2] = fmaf(f1.x, fm[c], v[2]); v[3] = fmaf(f1.y, fm[c], v[3]);
                v[4] = fmaf(f2.x, fm[c], v[4]); v[5] = fmaf(f2.y, fm[c], v[5]);
                v[6] = fmaf(f3.x, fm[c], v[6]); v[7] = fmaf(f3.y, fm[c], v[7]);
            }
            store_k4h(AsH, row, cid * 2,     make_float4(v[0], v[1], v[2], v[3]));
            store_k4h(AsH, row, cid * 2 + 1, make_float4(v[4], v[5], v[6], v[7]));
        }
    }
    __syncthreads();

    float acc[8][4];
    ACC_ZERO8(acc);
    gemm64h(AsH, g_Bfrag[1], wr, wc, lane, acc);

#pragma unroll
    for (int h = 0; h < 2; h++) {
        const int node = s + row0 + wr * 16 + (lane >> 2) + h * 8;
        const float mf = (float)mask[node];
        const size_t xm = (size_t)(x[node] * mask[node]);
#pragma unroll
        for (int nt = 0; nt < 8; nt++) {
            const int col = wc * 64 + nt * 8 + (lane & 3) * 2;
            float2 p = __half22float2(*(const __half2*)&g_Pbh[xm * 128 + col]);
            float o0 = tanhf(acc[nt][h * 2]     + p.x * mf);
            float o1 = tanhf(acc[nt][h * 2 + 1] + p.y * mf);
            *(__half2*)&g_hh[(size_t)node * 128 + col] = __floats2half2_rn(o0, o1);
        }
    }
}

// ---------------------------------------------------------------------------
// k_out_t: out[r0 .. r0+nrows) = g_hh @ W_out + b_out  (64 rows/block)
// A staging is a straight fp16 row copy (g_hh is already MMA-ready fp16).
// ---------------------------------------------------------------------------
__global__ void __launch_bounds__(256, 3)
k_out_t(int r0, int nrows, const float* __restrict__ b_out, float* __restrict__ out)
{
    extern __shared__ uint32_t sm[];
    uint32_t* AsH = sm;

    const int tid = threadIdx.x, wid = tid >> 5, lane = tid & 31;
    const int wr = wid & 3, wc = wid >> 2;
    const int row0 = r0 + blockIdx.x * 64;
    const int e = r0 + nrows;

    for (int i = tid; i < 2048; i += 256) {
        int row = i >> 5, q = i & 31;          // q indexes uint2 (2 uint32)
        int rr = row0 + row; if (rr >= e) rr = e - 1;
        uint2 v = ((const uint2*)(g_hh + (size_t)rr * 128))[q];
        AsH[row * KP + q * 2]     = v.x;
        AsH[row * KP + q * 2 + 1] = v.y;
    }
    __syncthreads();

    float acc[8][4];
    ACC_ZERO8(acc);
    gemm64h(AsH, g_Bfrag[2], wr, wc, lane, acc);

#pragma unroll
    for (int h = 0; h < 2; h++) {
        const int node = row0 + wr * 16 + (lane >> 2) + h * 8;
        if (node < e) {
#pragma unroll
            for (int nt = 0; nt < 8; nt++) {
                const int col = wc * 64 + nt * 8 + (lane & 3) * 2;
                float2 b = *(const float2*)&b_out[col];
                float2 o = make_float2(acc[nt][h * 2] + b.x,
                                       acc[nt][h * 2 + 1] + b.y);
                __stcs((float2*)&out[(size_t)node * 128 + col], o);
            }
        }
    }
}

// ---------------------------------------------------------------------------
// node-level FFMA body: 16 nodes per block-slot, 256 threads (fp16 h table)
// ---------------------------------------------------------------------------
__device__ __forceinline__ void nodes_body(int base, int s, int e,
                                           const int* __restrict__ x,
                                           const int* __restrict__ mask,
                                           const int* __restrict__ children,
                                           const float* __restrict__ U,
                                           float (*agg)[128])
{
    const int tid = threadIdx.x;
    const int col = tid & 127, half = tid >> 7;

#pragma unroll
    for (int g = 0; g < 8; g++) {
        const int node = base + half * 8 + g;
        const int nb = (node < e) ? node : s;
        float sum = 0.f;
#pragma unroll
        for (int c = 0; c < 8; c++)
            sum += __half2float(g_hh[(size_t)children[(size_t)nb * 8 + c] * 128 + col]);
        agg[half * 8 + g][col] = sum;
    }
    __syncthreads();

    float acc[8];
#pragma unroll
    for (int g = 0; g < 8; g++) acc[g] = 0.f;
#pragma unroll 4
    for (int k = 0; k < 128; k++) {
        const float u = __ldg(&U[k * 128 + col]);
#pragma unroll
        for (int g = 0; g < 8; g++)
            acc[g] = fmaf(agg[half * 8 + g][k], u, acc[g]);
    }

#pragma unroll
    for (int g = 0; g < 8; g++) {
        const int node = base + half * 8 + g;
        if (node < e) {
            const float mf = (float)mask[node];
            const int xm = x[node] * mask[node];
            const float hin = __half2float(g_Pbh[(size_t)xm * 128 + col]) * mf;
            g_hh[(size_t)node * 128 + col] = __float2half_rn(tanhf(hin + acc[g]));
        }
    }
}

__global__ void __launch_bounds__(256, 4)
k_nodes(int s, int n, const int* __restrict__ x, const int* __restrict__ mask,
        const int* __restrict__ children, const float* __restrict__ U)
{
    __shared__ float agg[16][128];
    nodes_body(s + blockIdx.x * 16, s, s + n, x, mask, children, U, agg);
}

__global__ void __launch_bounds__(256, 1)
k_tail(const int* __restrict__ x, const int* __restrict__ mask,
       const int* __restrict__ children, const float* __restrict__ U)
{
    __shared__ float agg[16][128];
    const int ls[3] = {9, 1, 0};
    const int ln[3] = {64, 8, 1};
    for (int lv = 0; lv < 3; lv++) {
        const int s = ls[lv], e = s + ln[lv];
        for (int base = s; base < e; base += 16) {
            nodes_body(base, s, e, x, mask, children, U, agg);
            __syncthreads();
        }
    }
}

// ---------------------------------------------------------------------------
// k_out_leaf: out[leaf] = mask * Q[x] + b_out   (fp16 Q gather, streaming st)
// ---------------------------------------------------------------------------
__global__ void __launch_bounds__(256)
k_out_leaf(const int* __restrict__ x, const int* __restrict__ mask,
           const float* __restrict__ b_out, float* __restrict__ out)
{
    const float4 bv = ((const float4*)b_out)[threadIdx.x & 31];
    int idx = blockIdx.x * 256 + threadIdx.x;
#pragma unroll
    for (int it = 0; it < 4; it++, idx += 8192 * 256) {
        const int rr = idx >> 5, c = idx & 31;
        const int node = NINT + rr;
        const int m = mask[node];
        const int xm = x[node] * m;
        const float mf = (float)m;
        uint2 qw = *(const uint2*)(g_Qh + (size_t)xm * 128 + c * 4);
        float2 q0 = __half22float2(*(const __half2*)&qw.x);
        float2 q1 = __half22float2(*(const __half2*)&qw.y);
        float4 o = make_float4(fmaf(q0.x, mf, bv.x), fmaf(q0.y, mf, bv.y),
                               fmaf(q1.x, mf, bv.z), fmaf(q1.y, mf, bv.w));
        __stcs(&((float4*)out)[(size_t)node * 32 + c], o);
    }
}

// ---------------------------------------------------------------------------
extern "C" void kernel_launch(void* const* d_in, const int* in_sizes, int n_in,
                              void* d_out, int out_size)
{
    const int*   x        = (const int*)  d_in[0];
    const int*   mask     = (const int*)  d_in[1];
    const int*   children = (const int*)  d_in[2];
    const float* emb      = (const float*)d_in[3];
    const float* W_in     = (const float*)d_in[4];
    const float* b_in     = (const float*)d_in[5];
    const float* U        = (const float*)d_in[6];
    const float* W_out    = (const float*)d_in[7];
    const float* b_out    = (const float*)d_in[8];
    float*       out      = (float*)d_out;
    (void)in_sizes; (void)n_in; (void)out_size;

    static cudaStream_t sA = nullptr, sB = nullptr;
    static cudaEvent_t  eT, eH5, eJ1, eJ2;
    if (!sA) {
        cudaStreamCreateWithFlags(&sA, cudaStreamNonBlocking);
        cudaStreamCreateWithFlags(&sB, cudaStreamNonBlocking);
        cudaEventCreateWithFlags(&eT,  cudaEventDisableTiming);
        cudaEventCreateWithFlags(&eH5, cudaEventDisableTiming);
        cudaEventCreateWithFlags(&eJ1, cudaEventDisableTiming);
        cudaEventCreateWithFlags(&eJ2, cudaEventDisableTiming);
    }
    cudaStream_t s0 = 0;

    k_prep<<<48, 256, 0, s0>>>(W_in, U, W_out);
    // Pb, T, Q (fused, fp16 tables)
    k_vocab<<<500, 256, SMEM_BYTES, s0>>>(emb, b_in);
    cudaEventRecord(eT, s0);

    // side stream A: leaf outputs (needs Q only)
    cudaStreamWaitEvent(sA, eT, 0);
    k_out_leaf<<<8192, 256, 0, sA>>>(x, mask, b_out, out);
    cudaEventRecord(eJ1, sA);

    // critical path: level 5 hidden
    k_level5<<<512, 256, SMEM_BYTES, s0>>>(4681, x, mask, children);
    cudaEventRecord(eH5, s0);

    // side stream B: output GEMM for L5 rows
    cudaStreamWaitEvent(sB, eH5, 0);
    k_out_t<<<512, 256, SMEM_BYTES, sB>>>(4681, 32768, b_out, out);
    cudaEventRecord(eJ2, sB);

    // critical path: L4..L0, then output head
    k_nodes<<<256, 256, 0, s0>>>(585, 4096, x, mask, children, U); // L4
    k_nodes<<< 32, 256, 0, s0>>>( 73,  512, x, mask, children, U); // L3
    k_tail <<<  1, 256, 0, s0>>>(x, mask, children, U);            // L2..L0
    k_out_t<<<74, 256, SMEM_BYTES, s0>>>(0, 4681, b_out, out);     // out rows 0..4681

    cudaStreamWaitEvent(s0, eJ1, 0);
    cudaStreamWaitEvent(s0, eJ2, 0);
}

// round 14
// speedup vs baseline: 1.3798x; 1.1136x over previous
#include <cuda_runtime.h>
#include <cuda_fp16.h>
#include <math.h>
#include <stdint.h>

#define NINT 37449
#define NVOC 32000

// ---------------- device scratch (no allocs allowed) ----------------
static __device__ __half g_Pbh[(size_t)NVOC * 128]; // emb@W_in + b_in   (fp16)
static __device__ __half g_Th [(size_t)NVOC * 128]; // tanh(Pb)          (fp16)
static __device__ __half g_Qh [(size_t)NVOC * 128]; // T@W_out           (fp16)
static __device__ __half g_hh [(size_t)NINT * 128]; // hidden, internal  (fp16)
static __device__ uint4  g_Bfrag[2][4096];          // {Win,U}: {bh0,bh1,bl0,bl1} fp16x2 split
static __device__ uint2  g_BfragS[4096];            // Wout: single fp16 frags

// smem: AsH[64][68] packed fp16x2
#define KP 68
#define SMEM_BYTES (64 * KP * 4)   // 17408

__device__ __forceinline__ uint32_t pack_h2(float v0, float v1) {
    __half2 h = __floats2half2_rn(v0, v1);
    return *(uint32_t*)&h;
}

__device__ __forceinline__ void store_k4h(uint32_t* AsH, int row, int f4, float4 v) {
    const int o = row * KP + f4 * 2;
    AsH[o]     = pack_h2(v.x, v.y);
    AsH[o + 1] = pack_h2(v.z, v.w);
}

__device__ __forceinline__ void mma16h(float d[4], const uint32_t a[4],
                                       uint32_t b0, uint32_t b1) {
    asm volatile(
        "mma.sync.aligned.m16n8k16.row.col.f32.f16.f16.f32 "
        "{%0,%1,%2,%3}, {%4,%5,%6,%7}, {%8,%9}, {%0,%1,%2,%3};"
        : "+f"(d[0]), "+f"(d[1]), "+f"(d[2]), "+f"(d[3])
        : "r"(a[0]), "r"(a[1]), "r"(a[2]), "r"(a[3]), "r"(b0), "r"(b1));
}

// 64x128x128 tile GEMM, fp16: single A x (Bhi + Blo). 2 MMAs per (ks,nt).
__device__ __forceinline__ void gemm64h(const uint32_t* __restrict__ AsH,
                                        const uint4* __restrict__ Bf,
                                        int wr, int wc, int lane,
                                        float acc[8][4])
{
    const int rA = wr * 16 + (lane >> 2);
    const int cA = lane & 3;
#pragma unroll
    for (int ks = 0; ks < 8; ks++) {
        uint32_t ah[4];
        const int kpb = ks * 8 + cA;
        ah[0] = AsH[rA * KP + kpb];
        ah[1] = AsH[(rA + 8) * KP + kpb];
        ah[2] = AsH[rA * KP + kpb + 4];
        ah[3] = AsH[(rA + 8) * KP + kpb + 4];
#pragma unroll
        for (int nt = 0; nt < 8; nt++) {
            uint4 b = __ldg(&Bf[(ks * 16 + wc * 8 + nt) * 32 + lane]);
            mma16h(acc[nt], ah, b.x, b.y);   // A * B_hi
            mma16h(acc[nt], ah, b.z, b.w);   // A * B_lo
        }
    }
}

// 64x128x128 tile GEMM, fp16: single A x single B. 1 MMA per (ks,nt).
__device__ __forceinline__ void gemm64s(const uint32_t* __restrict__ AsH,
                                        const uint2* __restrict__ Bf,
                                        int wr, int wc, int lane,
                                        float acc[8][4])
{
    const int rA = wr * 16 + (lane >> 2);
    const int cA = lane & 3;
#pragma unroll
    for (int ks = 0; ks < 8; ks++) {
        uint32_t ah[4];
        const int kpb = ks * 8 + cA;
        ah[0] = AsH[rA * KP + kpb];
        ah[1] = AsH[(rA + 8) * KP + kpb];
        ah[2] = AsH[rA * KP + kpb + 4];
        ah[3] = AsH[(rA + 8) * KP + kpb + 4];
#pragma unroll
        for (int nt = 0; nt < 8; nt++) {
            uint2 b = __ldg(&Bf[(ks * 16 + wc * 8 + nt) * 32 + lane]);
            mma16h(acc[nt], ah, b.x, b.y);
        }
    }
}

#define ACC_ZERO8(acc) do { \
    _Pragma("unroll") for (int _b = 0; _b < 8; _b++) \
    _Pragma("unroll") for (int _c = 0; _c < 4; _c++) acc[_b][_c] = 0.f; } while (0)

// ---------------------------------------------------------------------------
// k_prep: B fragments. Win,U: fp16 2-term split. Wout: single fp16.
// ---------------------------------------------------------------------------
__global__ void k_prep(const float* __restrict__ Win, const float* __restrict__ U,
                       const float* __restrict__ Wout)
{
    int i = blockIdx.x * 256 + threadIdx.x;
    if (i < 3 * 4096) {
        int w = i >> 12, r = i & 4095;
        int ks = r >> 9, ng = (r >> 5) & 15, lane = r & 31;
        int n = ng * 8 + (lane >> 2);
        int k0 = ks * 16 + (lane & 3) * 2;
        const float* W = (w == 0) ? Win : ((w == 1) ? U : Wout);
        float v00 = W[k0 * 128 + n],       v01 = W[(k0 + 1) * 128 + n];
        float v10 = W[(k0 + 8) * 128 + n], v11 = W[(k0 + 9) * 128 + n];
        if (w < 2) {
            float h00 = __half2float(__float2half_rn(v00));
            float h01 = __half2float(__float2half_rn(v01));
            float h10 = __half2float(__float2half_rn(v10));
            float h11 = __half2float(__float2half_rn(v11));
            g_Bfrag[w][r] = make_uint4(pack_h2(h00, h01), pack_h2(h10, h11),
                                       pack_h2(v00 - h00, v01 - h01),
                                       pack_h2(v10 - h10, v11 - h11));
        } else {
            g_BfragS[r] = make_uint2(pack_h2(v00, v01), pack_h2(v10, v11));
        }
    }
}

// ---------------------------------------------------------------------------
// k_vocab1: Pb = emb@W_in + b_in; T = tanh(Pb)   (64 rows/block)
// ---------------------------------------------------------------------------
__global__ void __launch_bounds__(256, 3)
k_vocab1(const float* __restrict__ emb, const float* __restrict__ b_in)
{
    extern __shared__ uint32_t sm[];
    uint32_t* AsH = sm;

    const int tid = threadIdx.x, wid = tid >> 5, lane = tid & 31;
    const int wr = wid & 3, wc = wid >> 2;
    const int row0 = blockIdx.x * 64;

    for (int i = tid; i < 2048; i += 256) {
        int row = i >> 5, q = i & 31;
        float4 v = ((const float4*)emb)[(size_t)(row0 + row) * 32 + q];
        store_k4h(AsH, row, q, v);
    }
    __syncthreads();

    float acc[8][4];
    ACC_ZERO8(acc);
    gemm64h(AsH, g_Bfrag[0], wr, wc, lane, acc);

#pragma unroll
    for (int h = 0; h < 2; h++) {
        const size_t node = row0 + wr * 16 + (lane >> 2) + h * 8;
#pragma unroll
        for (int nt = 0; nt < 8; nt++) {
            const int col = wc * 64 + nt * 8 + (lane & 3) * 2;
            float2 b = *(const float2*)&b_in[col];
            float p0 = acc[nt][h * 2]     + b.x;
            float p1 = acc[nt][h * 2 + 1] + b.y;
            *(__half2*)&g_Pbh[node * 128 + col] = __floats2half2_rn(p0, p1);
            *(__half2*)&g_Th[node * 128 + col] =
                __floats2half2_rn(tanhf(p0), tanhf(p1));
        }
    }
}

// ---------------------------------------------------------------------------
// k_vocab2: Q = T @ W_out  (A staging = straight fp16 row copy)
// ---------------------------------------------------------------------------
__global__ void __launch_bounds__(256, 3)
k_vocab2()
{
    extern __shared__ uint32_t sm[];
    uint32_t* AsH = sm;

    const int tid = threadIdx.x, wid = tid >> 5, lane = tid & 31;
    const int wr = wid & 3, wc = wid >> 2;
    const int row0 = blockIdx.x * 64;

    for (int i = tid; i < 2048; i += 256) {
        int row = i >> 5, q = i & 31;
        uint2 v = ((const uint2*)(g_Th + (size_t)(row0 + row) * 128))[q];
        AsH[row * KP + q * 2]     = v.x;
        AsH[row * KP + q * 2 + 1] = v.y;
    }
    __syncthreads();

    float acc[8][4];
    ACC_ZERO8(acc);
    gemm64s(AsH, g_BfragS, wr, wc, lane, acc);

#pragma unroll
    for (int h = 0; h < 2; h++) {
        const size_t node = row0 + wr * 16 + (lane >> 2) + h * 8;
#pragma unroll
        for (int nt = 0; nt < 8; nt++) {
            const int col = wc * 64 + nt * 8 + (lane & 3) * 2;
            *(__half2*)&g_Qh[node * 128 + col] =
                __floats2half2_rn(acc[nt][h * 2], acc[nt][h * 2 + 1]);
        }
    }
}

// ---------------------------------------------------------------------------
// k_level5: h[node] = tanh(Pb[x*m]*m + (sum_c m_c*T[x_c]) @ U)  (64 rows/block)
// ---------------------------------------------------------------------------
__global__ void __launch_bounds__(256, 3)
k_level5(int s, const int* __restrict__ x, const int* __restrict__ mask,
         const int* __restrict__ children)
{
    extern __shared__ uint32_t sm[];
    uint32_t* AsH = sm;

    const int tid = threadIdx.x, wid = tid >> 5, lane = tid & 31;
    const int wr = wid & 3, wc = wid >> 2;
    const int row0 = blockIdx.x * 64;

    {
        const int row = tid >> 2, q4 = tid & 3;
        const int node = s + row0 + row;
        const __half* tp[8];
        float fm[8];
#pragma unroll
        for (int c = 0; c < 8; c++) {
            const int cc = children[(size_t)node * 8 + c];
            const int mm = mask[cc];
            tp[c] = g_Th + (size_t)(x[cc] * mm) * 128;
            fm[c] = (float)mm;
        }
#pragma unroll
        for (int j = 0; j < 4; j++) {
            const int cid = j * 4 + q4;      // 16-byte chunk = 8 halves
            float v[8];
#pragma unroll
            for (int k = 0; k < 8; k++) v[k] = 0.f;
#pragma unroll
            for (int c = 0; c < 8; c++) {
                uint4 w = *(const uint4*)(tp[c] + cid * 8);
                float2 f0 = __half22float2(*(const __half2*)&w.x);
                float2 f1 = __half22float2(*(const __half2*)&w.y);
                float2 f2 = __half22float2(*(const __half2*)&w.z);
                float2 f3 = __half22float2(*(const __half2*)&w.w);
                v[0] = fmaf(f0.x, fm[c], v[0]); v[1] = fmaf(f0.y, fm[c], v[1]);
                v[2] = fmaf(f1.x, fm[c], v[2]); v[3] = fmaf(f1.y, fm[c], v[3]);
                v[4] = fmaf(f2.x, fm[c], v[4]); v[5] = fmaf(f2.y, fm[c], v[5]);
                v[6] = fmaf(f3.x, fm[c], v[6]); v[7] = fmaf(f3.y, fm[c], v[7]);
            }
            store_k4h(AsH, row, cid * 2,     make_float4(v[0], v[1], v[2], v[3]));
            store_k4h(AsH, row, cid * 2 + 1, make_float4(v[4], v[5], v[6], v[7]));
        }
    }
    __syncthreads();

    float acc[8][4];
    ACC_ZERO8(acc);
    gemm64h(AsH, g_Bfrag[1], wr, wc, lane, acc);

#pragma unroll
    for (int h = 0; h < 2; h++) {
        const int node = s + row0 + wr * 16 + (lane >> 2) + h * 8;
        const float mf = (float)mask[node];
        const size_t xm = (size_t)(x[node] * mask[node]);
#pragma unroll
        for (int nt = 0; nt < 8; nt++) {
            const int col = wc * 64 + nt * 8 + (lane & 3) * 2;
            float2 p = __half22float2(*(const __half2*)&g_Pbh[xm * 128 + col]);
            float o0 = tanhf(acc[nt][h * 2]     + p.x * mf);
            float o1 = tanhf(acc[nt][h * 2 + 1] + p.y * mf);
            *(__half2*)&g_hh[(size_t)node * 128 + col] = __floats2half2_rn(o0, o1);
        }
    }
}

// ---------------------------------------------------------------------------
// k_out_t: out[r0 .. r0+nrows) = g_hh @ W_out + b_out  (single-fp16 W_out)
// ---------------------------------------------------------------------------
__global__ void __launch_bounds__(256, 3)
k_out_t(int r0, int nrows, const float* __restrict__ b_out, float* __restrict__ out)
{
    extern __shared__ uint32_t sm[];
    uint32_t* AsH = sm;

    const int tid = threadIdx.x, wid = tid >> 5, lane = tid & 31;
    const int wr = wid & 3, wc = wid >> 2;
    const int row0 = r0 + blockIdx.x * 64;
    const int e = r0 + nrows;

    for (int i = tid; i < 2048; i += 256) {
        int row = i >> 5, q = i & 31;
        int rr = row0 + row; if (rr >= e) rr = e - 1;
        uint2 v = ((const uint2*)(g_hh + (size_t)rr * 128))[q];
        AsH[row * KP + q * 2]     = v.x;
        AsH[row * KP + q * 2 + 1] = v.y;
    }
    __syncthreads();

    float acc[8][4];
    ACC_ZERO8(acc);
    gemm64s(AsH, g_BfragS, wr, wc, lane, acc);

#pragma unroll
    for (int h = 0; h < 2; h++) {
        const int node = row0 + wr * 16 + (lane >> 2) + h * 8;
        if (node < e) {
#pragma unroll
            for (int nt = 0; nt < 8; nt++) {
                const int col = wc * 64 + nt * 8 + (lane & 3) * 2;
                float2 b = *(const float2*)&b_out[col];
                float2 o = make_float2(acc[nt][h * 2] + b.x,
                                       acc[nt][h * 2 + 1] + b.y);
                __stcs((float2*)&out[(size_t)node * 128 + col], o);
            }
        }
    }
}

// ---------------------------------------------------------------------------
// node-level FFMA body: 16 nodes per block-slot, 256 threads (fp16 h table)
// ---------------------------------------------------------------------------
__device__ __forceinline__ void nodes_body(int base, int s, int e,
                                           const int* __restrict__ x,
                                           const int* __restrict__ mask,
                                           const int* __restrict__ children,
                                           const float* __restrict__ U,
                                           float (*agg)[128])
{
    const int tid = threadIdx.x;
    const int col = tid & 127, half = tid >> 7;

#pragma unroll
    for (int g = 0; g < 8; g++) {
        const int node = base + half * 8 + g;
        const int nb = (node < e) ? node : s;
        float sum = 0.f;
#pragma unroll
        for (int c = 0; c < 8; c++)
            sum += __half2float(g_hh[(size_t)children[(size_t)nb * 8 + c] * 128 + col]);
        agg[half * 8 + g][col] = sum;
    }
    __syncthreads();

    float acc[8];
#pragma unroll
    for (int g = 0; g < 8; g++) acc[g] = 0.f;
#pragma unroll 4
    for (int k = 0; k < 128; k++) {
        const float u = __ldg(&U[k * 128 + col]);
#pragma unroll
        for (int g = 0; g < 8; g++)
            acc[g] = fmaf(agg[half * 8 + g][k], u, acc[g]);
    }

#pragma unroll
    for (int g = 0; g < 8; g++) {
        const int node = base + half * 8 + g;
        if (node < e) {
            const float mf = (float)mask[node];
            const int xm = x[node] * mask[node];
            const float hin = __half2float(g_Pbh[(size_t)xm * 128 + col]) * mf;
            g_hh[(size_t)node * 128 + col] = __float2half_rn(tanhf(hin + acc[g]));
        }
    }
}

__global__ void __launch_bounds__(256, 4)
k_nodes(int s, int n, const int* __restrict__ x, const int* __restrict__ mask,
        const int* __restrict__ children, const float* __restrict__ U)
{
    __shared__ float agg[16][128];
    nodes_body(s + blockIdx.x * 16, s, s + n, x, mask, children, U, agg);
}

__global__ void __launch_bounds__(256, 1)
k_tail(const int* __restrict__ x, const int* __restrict__ mask,
       const int* __restrict__ children, const float* __restrict__ U)
{
    __shared__ float agg[16][128];
    const int ls[3] = {9, 1, 0};
    const int ln[3] = {64, 8, 1};
    for (int lv = 0; lv < 3; lv++) {
        const int s = ls[lv], e = s + ln[lv];
        for (int base = s; base < e; base += 16) {
            nodes_body(base, s, e, x, mask, children, U, agg);
            __syncthreads();
        }
    }
}

// ---------------------------------------------------------------------------
// k_out_leaf: out[leaf] = mask * Q[x] + b_out   (fp16 Q gather, streaming st)
// ---------------------------------------------------------------------------
__global__ void __launch_bounds__(256)
k_out_leaf(const int* __restrict__ x, const int* __restrict__ mask,
           const float* __restrict__ b_out, float* __restrict__ out)
{
    const float4 bv = ((const float4*)b_out)[threadIdx.x & 31];
    int idx = blockIdx.x * 256 + threadIdx.x;
#pragma unroll
    for (int it = 0; it < 4; it++, idx += 8192 * 256) {
        const int rr = idx >> 5, c = idx & 31;
        const int node = NINT + rr;
        const int m = mask[node];
        const int xm = x[node] * m;
        const float mf = (float)m;
        uint2 qw = *(const uint2*)(g_Qh + (size_t)xm * 128 + c * 4);
        float2 q0 = __half22float2(*(const __half2*)&qw.x);
        float2 q1 = __half22float2(*(const __half2*)&qw.y);
        float4 o = make_float4(fmaf(q0.x, mf, bv.x), fmaf(q0.y, mf, bv.y),
                               fmaf(q1.x, mf, bv.z), fmaf(q1.y, mf, bv.w));
        __stcs(&((float4*)out)[(size_t)node * 32 + c], o);
    }
}

// ---------------------------------------------------------------------------
extern "C" void kernel_launch(void* const* d_in, const int* in_sizes, int n_in,
                              void* d_out, int out_size)
{
    const int*   x        = (const int*)  d_in[0];
    const int*   mask     = (const int*)  d_in[1];
    const int*   children = (const int*)  d_in[2];
    const float* emb      = (const float*)d_in[3];
    const float* W_in     = (const float*)d_in[4];
    const float* b_in     = (const float*)d_in[5];
    const float* U        = (const float*)d_in[6];
    const float* W_out    = (const float*)d_in[7];
    const float* b_out    = (const float*)d_in[8];
    float*       out      = (float*)d_out;
    (void)in_sizes; (void)n_in; (void)out_size;

    static cudaStream_t sA = nullptr, sB = nullptr;
    static cudaEvent_t  eT, eH5, eJ1, eJ2;
    if (!sA) {
        cudaStreamCreateWithFlags(&sA, cudaStreamNonBlocking);
        cudaStreamCreateWithFlags(&sB, cudaStreamNonBlocking);
        cudaEventCreateWithFlags(&eT,  cudaEventDisableTiming);
        cudaEventCreateWithFlags(&eH5, cudaEventDisableTiming);
        cudaEventCreateWithFlags(&eJ1, cudaEventDisableTiming);
        cudaEventCreateWithFlags(&eJ2, cudaEventDisableTiming);
    }
    cudaStream_t s0 = 0;

    k_prep<<<48, 256, 0, s0>>>(W_in, U, W_out);
    // critical path: Pb, T only
    k_vocab1<<<500, 256, SMEM_BYTES, s0>>>(emb, b_in);
    cudaEventRecord(eT, s0);

    // side stream A: Q = T@W_out, then leaf outputs
    cudaStreamWaitEvent(sA, eT, 0);
    k_vocab2<<<500, 256, SMEM_BYTES, sA>>>();
    k_out_leaf<<<8192, 256, 0, sA>>>(x, mask, b_out, out);
    cudaEventRecord(eJ1, sA);

    // critical path: level 5 hidden
    k_level5<<<512, 256, SMEM_BYTES, s0>>>(4681, x, mask, children);
    cudaEventRecord(eH5, s0);

    // side stream B: output GEMM for L5 rows
    cudaStreamWaitEvent(sB, eH5, 0);
    k_out_t<<<512, 256, SMEM_BYTES, sB>>>(4681, 32768, b_out, out);
    cudaEventRecord(eJ2, sB);

    // critical path: L4..L0, then output head
    k_nodes<<<256, 256, 0, s0>>>(585, 4096, x, mask, children, U); // L4
    k_nodes<<< 32, 256, 0, s0>>>( 73,  512, x, mask, children, U); // L3
    k_tail <<<  1, 256, 0, s0>>>(x, mask, children, U);            // L2..L0
    k_out_t<<<74, 256, SMEM_BYTES, s0>>>(0, 4681, b_out, out);     // out rows 0..4681

    cudaStreamWaitEvent(s0, eJ1, 0);
    cudaStreamWaitEvent(s0, eJ2, 0);
}

// round 15
// speedup vs baseline: 1.4235x; 1.0317x over previous
#include <cuda_runtime.h>
#include <cuda_fp16.h>
#include <math.h>
#include <stdint.h>

#define NINT 37449
#define NVOC 32000

// ---------------- device scratch (no allocs allowed) ----------------
static __device__ __half g_Pbh[(size_t)NVOC * 128]; // emb@W_in + b_in   (fp16)
static __device__ __half g_Th [(size_t)NVOC * 128]; // tanh(Pb)          (fp16)
static __device__ __half g_Qh [(size_t)NVOC * 128]; // T@W_out           (fp16)
static __device__ __half g_hh [(size_t)NINT * 128]; // hidden, internal  (fp16)
static __device__ uint4  g_Bfrag[2][4096];          // {Win,U}: {bh0,bh1,bl0,bl1} fp16x2 split
static __device__ uint2  g_BfragS[4096];            // Wout: single fp16 frags

// smem: AsH[64][68] packed fp16x2
#define KP 68
#define SMEM_BYTES (64 * KP * 4)   // 17408

__device__ __forceinline__ uint32_t pack_h2(float v0, float v1) {
    __half2 h = __floats2half2_rn(v0, v1);
    return *(uint32_t*)&h;
}

__device__ __forceinline__ void store_k4h(uint32_t* AsH, int row, int f4, float4 v) {
    const int o = row * KP + f4 * 2;
    AsH[o]     = pack_h2(v.x, v.y);
    AsH[o + 1] = pack_h2(v.z, v.w);
}

__device__ __forceinline__ void mma16h(float d[4], const uint32_t a[4],
                                       uint32_t b0, uint32_t b1) {
    asm volatile(
        "mma.sync.aligned.m16n8k16.row.col.f32.f16.f16.f32 "
        "{%0,%1,%2,%3}, {%4,%5,%6,%7}, {%8,%9}, {%0,%1,%2,%3};"
        : "+f"(d[0]), "+f"(d[1]), "+f"(d[2]), "+f"(d[3])
        : "r"(a[0]), "r"(a[1]), "r"(a[2]), "r"(a[3]), "r"(b0), "r"(b1));
}

// 64x128x128 tile GEMM, fp16: single A x (Bhi + Blo). 2 MMAs per (ks,nt).
__device__ __forceinline__ void gemm64h(const uint32_t* __restrict__ AsH,
                                        const uint4* __restrict__ Bf,
                                        int wr, int wc, int lane,
                                        float acc[8][4])
{
    const int rA = wr * 16 + (lane >> 2);
    const int cA = lane & 3;
#pragma unroll
    for (int ks = 0; ks < 8; ks++) {
        uint32_t ah[4];
        const int kpb = ks * 8 + cA;
        ah[0] = AsH[rA * KP + kpb];
        ah[1] = AsH[(rA + 8) * KP + kpb];
        ah[2] = AsH[rA * KP + kpb + 4];
        ah[3] = AsH[(rA + 8) * KP + kpb + 4];
#pragma unroll
        for (int nt = 0; nt < 8; nt++) {
            uint4 b = __ldg(&Bf[(ks * 16 + wc * 8 + nt) * 32 + lane]);
            mma16h(acc[nt], ah, b.x, b.y);   // A * B_hi
            mma16h(acc[nt], ah, b.z, b.w);   // A * B_lo
        }
    }
}

// 64x128x128 tile GEMM, fp16: single A x single B. 1 MMA per (ks,nt).
__device__ __forceinline__ void gemm64s(const uint32_t* __restrict__ AsH,
                                        const uint2* __restrict__ Bf,
                                        int wr, int wc, int lane,
                                        float acc[8][4])
{
    const int rA = wr * 16 + (lane >> 2);
    const int cA = lane & 3;
#pragma unroll
    for (int ks = 0; ks < 8; ks++) {
        uint32_t ah[4];
        const int kpb = ks * 8 + cA;
        ah[0] = AsH[rA * KP + kpb];
        ah[1] = AsH[(rA + 8) * KP + kpb];
        ah[2] = AsH[rA * KP + kpb + 4];
        ah[3] = AsH[(rA + 8) * KP + kpb + 4];
#pragma unroll
        for (int nt = 0; nt < 8; nt++) {
            uint2 b = __ldg(&Bf[(ks * 16 + wc * 8 + nt) * 32 + lane]);
            mma16h(acc[nt], ah, b.x, b.y);
        }
    }
}

#define ACC_ZERO8(acc) do { \
    _Pragma("unroll") for (int _b = 0; _b < 8; _b++) \
    _Pragma("unroll") for (int _c = 0; _c < 4; _c++) acc[_b][_c] = 0.f; } while (0)

// ---------------------------------------------------------------------------
// k_prep: B fragments. Win,U: fp16 2-term split. Wout: single fp16.
// ---------------------------------------------------------------------------
__global__ void k_prep(const float* __restrict__ Win, const float* __restrict__ U,
                       const float* __restrict__ Wout)
{
    int i = blockIdx.x * 256 + threadIdx.x;
    if (i < 3 * 4096) {
        int w = i >> 12, r = i & 4095;
        int ks = r >> 9, ng = (r >> 5) & 15, lane = r & 31;
        int n = ng * 8 + (lane >> 2);
        int k0 = ks * 16 + (lane & 3) * 2;
        const float* W = (w == 0) ? Win : ((w == 1) ? U : Wout);
        float v00 = W[k0 * 128 + n],       v01 = W[(k0 + 1) * 128 + n];
        float v10 = W[(k0 + 8) * 128 + n], v11 = W[(k0 + 9) * 128 + n];
        if (w < 2) {
            float h00 = __half2float(__float2half_rn(v00));
            float h01 = __half2float(__float2half_rn(v01));
            float h10 = __half2float(__float2half_rn(v10));
            float h11 = __half2float(__float2half_rn(v11));
            g_Bfrag[w][r] = make_uint4(pack_h2(h00, h01), pack_h2(h10, h11),
                                       pack_h2(v00 - h00, v01 - h01),
                                       pack_h2(v10 - h10, v11 - h11));
        } else {
            g_BfragS[r] = make_uint2(pack_h2(v00, v01), pack_h2(v10, v11));
        }
    }
}

// ---------------------------------------------------------------------------
// k_vocab1: Pb = emb@W_in + b_in; T = tanh(Pb)   (64 rows/block)
// ---------------------------------------------------------------------------
__global__ void __launch_bounds__(256, 3)
k_vocab1(const float* __restrict__ emb, const float* __restrict__ b_in)
{
    extern __shared__ uint32_t sm[];
    uint32_t* AsH = sm;

    const int tid = threadIdx.x, wid = tid >> 5, lane = tid & 31;
    const int wr = wid & 3, wc = wid >> 2;
    const int row0 = blockIdx.x * 64;

    for (int i = tid; i < 2048; i += 256) {
        int row = i >> 5, q = i & 31;
        float4 v = ((const float4*)emb)[(size_t)(row0 + row) * 32 + q];
        store_k4h(AsH, row, q, v);
    }
    __syncthreads();

    float acc[8][4];
    ACC_ZERO8(acc);
    gemm64h(AsH, g_Bfrag[0], wr, wc, lane, acc);

#pragma unroll
    for (int h = 0; h < 2; h++) {
        const size_t node = row0 + wr * 16 + (lane >> 2) + h * 8;
#pragma unroll
        for (int nt = 0; nt < 8; nt++) {
            const int col = wc * 64 + nt * 8 + (lane & 3) * 2;
            float2 b = *(const float2*)&b_in[col];
            float p0 = acc[nt][h * 2]     + b.x;
            float p1 = acc[nt][h * 2 + 1] + b.y;
            *(__half2*)&g_Pbh[node * 128 + col] = __floats2half2_rn(p0, p1);
            *(__half2*)&g_Th[node * 128 + col] =
                __floats2half2_rn(tanhf(p0), tanhf(p1));
        }
    }
}

// ---------------------------------------------------------------------------
// k_vocab2: Q = T @ W_out  (A staging = straight fp16 row copy)
// ---------------------------------------------------------------------------
__global__ void __launch_bounds__(256, 3)
k_vocab2()
{
    extern __shared__ uint32_t sm[];
    uint32_t* AsH = sm;

    const int tid = threadIdx.x, wid = tid >> 5, lane = tid & 31;
    const int wr = wid & 3, wc = wid >> 2;
    const int row0 = blockIdx.x * 64;

    for (int i = tid; i < 2048; i += 256) {
        int row = i >> 5, q = i & 31;
        uint2 v = ((const uint2*)(g_Th + (size_t)(row0 + row) * 128))[q];
        AsH[row * KP + q * 2]     = v.x;
        AsH[row * KP + q * 2 + 1] = v.y;
    }
    __syncthreads();

    float acc[8][4];
    ACC_ZERO8(acc);
    gemm64s(AsH, g_BfragS, wr, wc, lane, acc);

#pragma unroll
    for (int h = 0; h < 2; h++) {
        const size_t node = row0 + wr * 16 + (lane >> 2) + h * 8;
#pragma unroll
        for (int nt = 0; nt < 8; nt++) {
            const int col = wc * 64 + nt * 8 + (lane & 3) * 2;
            *(__half2*)&g_Qh[node * 128 + col] =
                __floats2half2_rn(acc[nt][h * 2], acc[nt][h * 2 + 1]);
        }
    }
}

// ---------------------------------------------------------------------------
// k_level5f: h = tanh(Pb[x*m]*m + (sum_c m_c*T[x_c]) @ U); write g_hh; then
//            FUSED out[node] = h @ W_out + b_out.   64 rows/block.
// Staging accumulates children directly in half2 (HFMA2, no converts).
// ---------------------------------------------------------------------------
__global__ void __launch_bounds__(256, 3)
k_level5f(int s, const int* __restrict__ x, const int* __restrict__ mask,
          const int* __restrict__ children, const float* __restrict__ b_out,
          float* __restrict__ out)
{
    extern __shared__ uint32_t sm[];
    uint32_t* AsH = sm;

    const int tid = threadIdx.x, wid = tid >> 5, lane = tid & 31;
    const int wr = wid & 3, wc = wid >> 2;
    const int row0 = blockIdx.x * 64;

    {
        const int row = tid >> 2, q4 = tid & 3;
        const int node = s + row0 + row;
        const __half* tp[8];
        __half2 fm2[8];
#pragma unroll
        for (int c = 0; c < 8; c++) {
            const int cc = children[(size_t)node * 8 + c];
            const int mm = mask[cc];
            tp[c] = g_Th + (size_t)(x[cc] * mm) * 128;
            fm2[c] = __float2half2_rn((float)mm);
        }
        const __half2 z = __float2half2_rn(0.f);
#pragma unroll
        for (int j = 0; j < 4; j++) {
            const int cid = j * 4 + q4;      // 16-byte chunk = 8 halves
            __half2 a0 = z, a1 = z, a2 = z, a3 = z;
#pragma unroll
            for (int c = 0; c < 8; c++) {
                uint4 w = *(const uint4*)(tp[c] + cid * 8);
                a0 = __hfma2(*(const __half2*)&w.x, fm2[c], a0);
                a1 = __hfma2(*(const __half2*)&w.y, fm2[c], a1);
                a2 = __hfma2(*(const __half2*)&w.z, fm2[c], a2);
                a3 = __hfma2(*(const __half2*)&w.w, fm2[c], a3);
            }
            const int o = row * KP + cid * 4;
            AsH[o]     = *(uint32_t*)&a0;
            AsH[o + 1] = *(uint32_t*)&a1;
            AsH[o + 2] = *(uint32_t*)&a2;
            AsH[o + 3] = *(uint32_t*)&a3;
        }
    }
    __syncthreads();

    float acc[8][4];
    ACC_ZERO8(acc);
    gemm64h(AsH, g_Bfrag[1], wr, wc, lane, acc);

    // epilogue 1: h = tanh(acc + Pb*m); write g_hh; keep h in acc
#pragma unroll
    for (int h = 0; h < 2; h++) {
        const int node = s + row0 + wr * 16 + (lane >> 2) + h * 8;
        const float mf = (float)mask[node];
        const size_t xm = (size_t)(x[node] * mask[node]);
#pragma unroll
        for (int nt = 0; nt < 8; nt++) {
            const int col = wc * 64 + nt * 8 + (lane & 3) * 2;
            float2 p = __half22float2(*(const __half2*)&g_Pbh[xm * 128 + col]);
            float o0 = tanhf(acc[nt][h * 2]     + p.x * mf);
            float o1 = tanhf(acc[nt][h * 2 + 1] + p.y * mf);
            *(__half2*)&g_hh[(size_t)node * 128 + col] = __floats2half2_rn(o0, o1);
            acc[nt][h * 2]     = o0;
            acc[nt][h * 2 + 1] = o1;
        }
    }
    __syncthreads();   // all warps done reading AsH in pass 1
#pragma unroll
    for (int h = 0; h < 2; h++) {
        const int r = wr * 16 + (lane >> 2) + h * 8;
#pragma unroll
        for (int nt = 0; nt < 8; nt++) {
            const int col = wc * 64 + nt * 8 + (lane & 3) * 2;
            AsH[r * KP + (col >> 1)] = pack_h2(acc[nt][h * 2], acc[nt][h * 2 + 1]);
        }
    }
    __syncthreads();

    // pass 2: out = h @ W_out + b_out
    ACC_ZERO8(acc);
    gemm64s(AsH, g_BfragS, wr, wc, lane, acc);

#pragma unroll
    for (int h = 0; h < 2; h++) {
        const int node = s + row0 + wr * 16 + (lane >> 2) + h * 8;
#pragma unroll
        for (int nt = 0; nt < 8; nt++) {
            const int col = wc * 64 + nt * 8 + (lane & 3) * 2;
            float2 b = *(const float2*)&b_out[col];
            float2 o = make_float2(acc[nt][h * 2] + b.x,
                                   acc[nt][h * 2 + 1] + b.y);
            __stcs((float2*)&out[(size_t)node * 128 + col], o);
        }
    }
}

// ---------------------------------------------------------------------------
// k_out_t: out[r0 .. r0+nrows) = g_hh @ W_out + b_out  (single-fp16 W_out)
// ---------------------------------------------------------------------------
__global__ void __launch_bounds__(256, 3)
k_out_t(int r0, int nrows, const float* __restrict__ b_out, float* __restrict__ out)
{
    extern __shared__ uint32_t sm[];
    uint32_t* AsH = sm;

    const int tid = threadIdx.x, wid = tid >> 5, lane = tid & 31;
    const int wr = wid & 3, wc = wid >> 2;
    const int row0 = r0 + blockIdx.x * 64;
    const int e = r0 + nrows;

    for (int i = tid; i < 2048; i += 256) {
        int row = i >> 5, q = i & 31;
        int rr = row0 + row; if (rr >= e) rr = e - 1;
        uint2 v = ((const uint2*)(g_hh + (size_t)rr * 128))[q];
        AsH[row * KP + q * 2]     = v.x;
        AsH[row * KP + q * 2 + 1] = v.y;
    }
    __syncthreads();

    float acc[8][4];
    ACC_ZERO8(acc);
    gemm64s(AsH, g_BfragS, wr, wc, lane, acc);

#pragma unroll
    for (int h = 0; h < 2; h++) {
        const int node = row0 + wr * 16 + (lane >> 2) + h * 8;
        if (node < e) {
#pragma unroll
            for (int nt = 0; nt < 8; nt++) {
                const int col = wc * 64 + nt * 8 + (lane & 3) * 2;
                float2 b = *(const float2*)&b_out[col];
                float2 o = make_float2(acc[nt][h * 2] + b.x,
                                       acc[nt][h * 2 + 1] + b.y);
                __stcs((float2*)&out[(size_t)node * 128 + col], o);
            }
        }
    }
}

// ---------------------------------------------------------------------------
// node-level FFMA body: 16 nodes per block-slot, 256 threads (fp16 h table)
// ---------------------------------------------------------------------------
__device__ __forceinline__ void nodes_body(int base, int s, int e,
                                           const int* __restrict__ x,
                                           const int* __restrict__ mask,
                                           const int* __restrict__ children,
                                           const float* __restrict__ U,
                                           float (*agg)[128])
{
    const int tid = threadIdx.x;
    const int col = tid & 127, half = tid >> 7;

#pragma unroll
    for (int g = 0; g < 8; g++) {
        const int node = base + half * 8 + g;
        const int nb = (node < e) ? node : s;
        float sum = 0.f;
#pragma unroll
        for (int c = 0; c < 8; c++)
            sum += __half2float(g_hh[(size_t)children[(size_t)nb * 8 + c] * 128 + col]);
        agg[half * 8 + g][col] = sum;
    }
    __syncthreads();

    float acc[8];
#pragma unroll
    for (int g = 0; g < 8; g++) acc[g] = 0.f;
#pragma unroll 4
    for (int k = 0; k < 128; k++) {
        const float u = __ldg(&U[k * 128 + col]);
#pragma unroll
        for (int g = 0; g < 8; g++)
            acc[g] = fmaf(agg[half * 8 + g][k], u, acc[g]);
    }

#pragma unroll
    for (int g = 0; g < 8; g++) {
        const int node = base + half * 8 + g;
        if (node < e) {
            const float mf = (float)mask[node];
            const int xm = x[node] * mask[node];
            const float hin = __half2float(g_Pbh[(size_t)xm * 128 + col]) * mf;
            g_hh[(size_t)node * 128 + col] = __float2half_rn(tanhf(hin + acc[g]));
        }
    }
}

__global__ void __launch_bounds__(256, 4)
k_nodes(int s, int n, const int* __restrict__ x, const int* __restrict__ mask,
        const int* __restrict__ children, const float* __restrict__ U)
{
    __shared__ float agg[16][128];
    nodes_body(s + blockIdx.x * 16, s, s + n, x, mask, children, U, agg);
}

__global__ void __launch_bounds__(256, 1)
k_tail(const int* __restrict__ x, const int* __restrict__ mask,
       const int* __restrict__ children, const float* __restrict__ U)
{
    __shared__ float agg[16][128];
    const int ls[3] = {9, 1, 0};
    const int ln[3] = {64, 8, 1};
    for (int lv = 0; lv < 3; lv++) {
        const int s = ls[lv], e = s + ln[lv];
        for (int base = s; base < e; base += 16) {
            nodes_body(base, s, e, x, mask, children, U, agg);
            __syncthreads();
        }
    }
}

// ---------------------------------------------------------------------------
// k_out_leaf: out[leaf] = mask * Q[x] + b_out   (fp16 Q gather, streaming st)
// ---------------------------------------------------------------------------
__global__ void __launch_bounds__(256)
k_out_leaf(const int* __restrict__ x, const int* __restrict__ mask,
           const float* __restrict__ b_out, float* __restrict__ out)
{
    const float4 bv = ((const float4*)b_out)[threadIdx.x & 31];
    int idx = blockIdx.x * 256 + threadIdx.x;
#pragma unroll
    for (int it = 0; it < 4; it++, idx += 8192 * 256) {
        const int rr = idx >> 5, c = idx & 31;
        const int node = NINT + rr;
        const int m = mask[node];
        const int xm = x[node] * m;
        const float mf = (float)m;
        uint2 qw = *(const uint2*)(g_Qh + (size_t)xm * 128 + c * 4);
        float2 q0 = __half22float2(*(const __half2*)&qw.x);
        float2 q1 = __half22float2(*(const __half2*)&qw.y);
        float4 o = make_float4(fmaf(q0.x, mf, bv.x), fmaf(q0.y, mf, bv.y),
                               fmaf(q1.x, mf, bv.z), fmaf(q1.y, mf, bv.w));
        __stcs(&((float4*)out)[(size_t)node * 32 + c], o);
    }
}

// ---------------------------------------------------------------------------
extern "C" void kernel_launch(void* const* d_in, const int* in_sizes, int n_in,
                              void* d_out, int out_size)
{
    const int*   x        = (const int*)  d_in[0];
    const int*   mask     = (const int*)  d_in[1];
    const int*   children = (const int*)  d_in[2];
    const float* emb      = (const float*)d_in[3];
    const float* W_in     = (const float*)d_in[4];
    const float* b_in     = (const float*)d_in[5];
    const float* U        = (const float*)d_in[6];
    const float* W_out    = (const float*)d_in[7];
    const float* b_out    = (const float*)d_in[8];
    float*       out      = (float*)d_out;
    (void)in_sizes; (void)n_in; (void)out_size;

    static cudaStream_t sA = nullptr;
    static cudaEvent_t  eT, eJ1;
    if (!sA) {
        cudaStreamCreateWithFlags(&sA, cudaStreamNonBlocking);
        cudaEventCreateWithFlags(&eT,  cudaEventDisableTiming);
        cudaEventCreateWithFlags(&eJ1, cudaEventDisableTiming);
    }
    cudaStream_t s0 = 0;

    k_prep<<<48, 256, 0, s0>>>(W_in, U, W_out);
    // critical path: Pb, T only
    k_vocab1<<<500, 256, SMEM_BYTES, s0>>>(emb, b_in);
    cudaEventRecord(eT, s0);

    // side stream A: Q = T@W_out, then leaf outputs
    cudaStreamWaitEvent(sA, eT, 0);
    k_vocab2<<<500, 256, SMEM_BYTES, sA>>>();
    k_out_leaf<<<8192, 256, 0, sA>>>(x, mask, b_out, out);
    cudaEventRecord(eJ1, sA);

    // critical path: level 5 hidden + fused out rows 4681..37449
    k_level5f<<<512, 256, SMEM_BYTES, s0>>>(4681, x, mask, children, b_out, out);

    // critical path: L4..L0, then output head
    k_nodes<<<256, 256, 0, s0>>>(585, 4096, x, mask, children, U); // L4
    k_nodes<<< 32, 256, 0, s0>>>( 73,  512, x, mask, children, U); // L3
    k_tail <<<  1, 256, 0, s0>>>(x, mask, children, U);            // L2..L0
    k_out_t<<<74, 256, SMEM_BYTES, s0>>>(0, 4681, b_out, out);     // out rows 0..4681

    cudaStreamWaitEvent(s0, eJ1, 0);
}